// round 9
// baseline (speedup 1.0000x reference)
#include <cuda_runtime.h>
#include <cuda_bf16.h>
#include <math.h>
#include <stdint.h>

#define SQ   2048
#define NB   2
#define NH   16
#define DKH  64
#define DM   1024
#define MROWS 4096   // NB*SQ

// ---------------------------------------------------------------------------
// Scratch (__device__ globals; allocation-free rule)
// ---------------------------------------------------------------------------
__device__ float g_rope[SQ * 32 * 2];                    // cos,sin per (s,j)

// bf16 scratch offsets (elements; MROWS*DM = 4M, DM*DM = 1M)
#define BF_XHI  0ull
#define BF_XLO  (1ull * MROWS * DM)
#define BF_WT   (2ull * MROWS * DM)                       // 8 x DM*DM
#define BF_AHI  (BF_WT + 8ull * DM * DM)
#define BF_ALO  (BF_AHI + 1ull * MROWS * DM)
#define BF_QHI  (BF_ALO + 1ull * MROWS * DM)
#define BF_QLO  (BF_QHI + 1ull * MROWS * DM)
#define BF_KHI  (BF_QLO + 1ull * MROWS * DM)
#define BF_KLO  (BF_KHI + 1ull * MROWS * DM)
#define BF_VTHI (BF_KLO + 1ull * MROWS * DM)
#define BF_VTLO (BF_VTHI + 1ull * MROWS * DM)
__device__ __nv_bfloat16 g_bf[BF_VTLO + 1ull * MROWS * DM];

// ---------------------------------------------------------------------------
// Helpers (sm_100-safe: cp.async, ldmatrix, mma.sync only)
// ---------------------------------------------------------------------------
__device__ __forceinline__ uint32_t smem_u32(const void* p) {
    uint32_t a;
    asm("{ .reg .u64 t; cvta.to.shared.u64 t, %1; cvt.u32.u64 %0, t; }"
        : "=r"(a) : "l"(p));
    return a;
}

__device__ __forceinline__ uint32_t sw64(uint32_t off) {
    return off ^ ((off >> 3) & 0x30);
}
__device__ __forceinline__ uint32_t sw128(uint32_t off) {
    return off ^ ((off >> 3) & 0x70);
}

__device__ __forceinline__ void ldm_x4(uint32_t* r, uint32_t addr) {
    asm volatile("ldmatrix.sync.aligned.m8n8.x4.shared.b16 {%0,%1,%2,%3}, [%4];"
                 : "=r"(r[0]), "=r"(r[1]), "=r"(r[2]), "=r"(r[3]) : "r"(addr));
}
__device__ __forceinline__ void ldm_x2(uint32_t* r, uint32_t addr) {
    asm volatile("ldmatrix.sync.aligned.m8n8.x2.shared.b16 {%0,%1}, [%2];"
                 : "=r"(r[0]), "=r"(r[1]) : "r"(addr));
}

__device__ __forceinline__ void mma_bf16(float* d, const uint32_t* a,
                                         const uint32_t* b) {
    asm volatile(
        "mma.sync.aligned.m16n8k16.row.col.f32.bf16.bf16.f32 "
        "{%0,%1,%2,%3}, {%4,%5,%6,%7}, {%8,%9}, {%0,%1,%2,%3};"
        : "+f"(d[0]), "+f"(d[1]), "+f"(d[2]), "+f"(d[3])
        : "r"(a[0]), "r"(a[1]), "r"(a[2]), "r"(a[3]), "r"(b[0]), "r"(b[1]));
}

__device__ __forceinline__ void cp_async16(uint32_t dst, const void* src) {
    asm volatile("cp.async.cg.shared.global [%0], [%1], 16;"
                 :: "r"(dst), "l"(src));
}
#define CP_COMMIT() asm volatile("cp.async.commit_group;" ::: "memory")
#define CP_WAIT(n)  asm volatile("cp.async.wait_group %0;" :: "n"(n) : "memory")

__device__ __forceinline__ uint32_t packbf2(float a, float b) {
    __nv_bfloat162 t = __floats2bfloat162_rn(a, b);
    return *(uint32_t*)&t;
}

// ---------------------------------------------------------------------------
// Prep: fp32 -> (bf16 hi, bf16 lo) split, 4 elems/thread
// ---------------------------------------------------------------------------
__global__ __launch_bounds__(256) void split_kernel(
    const float* __restrict__ src, __nv_bfloat16* __restrict__ hi,
    __nv_bfloat16* __restrict__ lo)
{
    size_t i = (size_t)(blockIdx.x * 256 + threadIdx.x) * 4;
    float4 v = *(const float4*)(src + i);
    __nv_bfloat16 h0 = __float2bfloat16_rn(v.x);
    __nv_bfloat16 h1 = __float2bfloat16_rn(v.y);
    __nv_bfloat16 h2 = __float2bfloat16_rn(v.z);
    __nv_bfloat16 h3 = __float2bfloat16_rn(v.w);
    __nv_bfloat16 l0 = __float2bfloat16_rn(v.x - __bfloat162float(h0));
    __nv_bfloat16 l1 = __float2bfloat16_rn(v.y - __bfloat162float(h1));
    __nv_bfloat16 l2 = __float2bfloat16_rn(v.z - __bfloat162float(h2));
    __nv_bfloat16 l3 = __float2bfloat16_rn(v.w - __bfloat162float(h3));
    ((__nv_bfloat162*)(hi + i))[0] = __nv_bfloat162(h0, h1);
    ((__nv_bfloat162*)(hi + i))[1] = __nv_bfloat162(h2, h3);
    ((__nv_bfloat162*)(lo + i))[0] = __nv_bfloat162(l0, l1);
    ((__nv_bfloat162*)(lo + i))[1] = __nv_bfloat162(l2, l3);
}

// ---------------------------------------------------------------------------
// Prep: transpose + split the 4 weight matrices W[k][n] -> Wt_hi/lo[n][k]
// ---------------------------------------------------------------------------
__global__ __launch_bounds__(256) void wsplit_kernel(
    const float* __restrict__ W0, const float* __restrict__ W1,
    const float* __restrict__ W2, const float* __restrict__ W3)
{
    __shared__ float t[32][33];
    const float* W = (blockIdx.z == 0) ? W0 : (blockIdx.z == 1) ? W1
                   : (blockIdx.z == 2) ? W2 : W3;
    __nv_bfloat16* whi = g_bf + BF_WT + (size_t)(2 * blockIdx.z) * DM * DM;
    __nv_bfloat16* wlo = whi + (size_t)DM * DM;
    int tx = threadIdx.x, ty = threadIdx.y;
    int n = blockIdx.x * 32 + tx;
#pragma unroll
    for (int i = 0; i < 32; i += 8)
        t[ty + i][tx] = W[(size_t)(blockIdx.y * 32 + ty + i) * DM + n];
    __syncthreads();
#pragma unroll
    for (int i = 0; i < 32; i += 8) {
        float v = t[tx][ty + i];
        __nv_bfloat16 h = __float2bfloat16_rn(v);
        __nv_bfloat16 l = __float2bfloat16_rn(v - __bfloat162float(h));
        size_t o = (size_t)(blockIdx.x * 32 + ty + i) * DM + blockIdx.y * 32 + tx;
        whi[o] = h;
        wlo[o] = l;
    }
}

// ---------------------------------------------------------------------------
// RoPE cos/sin table: (s, j) -> g_rope[2*(s*32+j)] = {cos, sin}
// ---------------------------------------------------------------------------
__global__ __launch_bounds__(256) void rope_table_kernel()
{
    int i = blockIdx.x * 256 + threadIdx.x;   // 0 .. 65535
    int s = i >> 5, j = i & 31;
    float invf = (float)pow(10000.0, -(double)j / 32.0);
    float ang = (float)s * invf;
    float sn, c;
    sincosf(ang, &sn, &c);
    g_rope[2 * i]     = c;
    g_rope[2 * i + 1] = sn;
}

// ---------------------------------------------------------------------------
// mma.sync bf16-split GEMM, 3-stage cp.async pipeline, fused epilogues.
// MODE 0: C = acc + bias (fp32, row-major)
// MODE 1: Vt hi/lo bf16, transposed write [(bh*64+d)][s]  (acc+bias)
// MODE 2: RoPE (table) + optional 0.125 scale + bf16 hi/lo split, [m][n]
// ---------------------------------------------------------------------------
#define KCH 32
#define NKT (DM / KCH)             // 32 chunks
#define STG_T 8192
#define STG_B (4 * STG_T)          // 32 KB per stage
#define MM_SMEM (3 * STG_B + 1024)

template <int MODE>
__global__ __launch_bounds__(256, 2) void mm_gemm(
    const __nv_bfloat16* __restrict__ Ahi, const __nv_bfloat16* __restrict__ Alo,
    const __nv_bfloat16* __restrict__ Bhi, const __nv_bfloat16* __restrict__ Blo,
    const float* __restrict__ bias, float* __restrict__ C,
    __nv_bfloat16* __restrict__ Dhi, __nv_bfloat16* __restrict__ Dlo,
    int scaleQ)
{
    extern __shared__ char smraw[];
    const uint32_t sbase = (smem_u32(smraw) + 1023) & ~1023u;

    const int tid  = threadIdx.x;
    const int wid  = tid >> 5, lane = tid & 31;
    const int m0   = blockIdx.y * 128, n0 = blockIdx.x * 128;
    const int wm   = (wid >> 2) * 64, wn = (wid & 3) * 32;

    float acc[4][4][4];
#pragma unroll
    for (int i = 0; i < 4; i++)
#pragma unroll
        for (int j = 0; j < 4; j++)
#pragma unroll
            for (int r = 0; r < 4; r++) acc[i][j][r] = 0.f;

    auto load_stage = [&](int kt, int slot) {
        const uint32_t bb = sbase + slot * STG_B;
#pragma unroll
        for (int it = 0; it < 8; it++) {
            int i = it * 256 + tid;
            int tile = i >> 9, idx = i & 511;
            int r = idx >> 2, c = idx & 3;
            uint32_t dst = bb + tile * STG_T + sw64((uint32_t)(r * 64 + c * 16));
            size_t off = (tile < 2)
                ? (size_t)(m0 + r) * DM + kt * KCH + c * 8
                : (size_t)(n0 + r) * DM + kt * KCH + c * 8;
            const __nv_bfloat16* src =
                (tile == 0) ? Ahi + off : (tile == 1) ? Alo + off
              : (tile == 2) ? Bhi + off : Blo + off;
            cp_async16(dst, src);
        }
    };

    load_stage(0, 0); CP_COMMIT();
    load_stage(1, 1); CP_COMMIT();

    int slot = 0;
    for (int kt = 0; kt < NKT; kt++) {
        CP_WAIT(1);
        __syncthreads();
        if (kt + 2 < NKT) {
            int ns = slot + 2; if (ns >= 3) ns -= 3;
            load_stage(kt + 2, ns);
            CP_COMMIT();
        } else {
            CP_COMMIT();
        }

        const uint32_t bb = sbase + slot * STG_B;
#pragma unroll
        for (int ks = 0; ks < 2; ks++) {
            uint32_t ah[4][4], al[4][4];
#pragma unroll
            for (int mt = 0; mt < 4; mt++) {
                int row = wm + mt * 16 + (lane & 15);
                int c = ks * 2 + (lane >> 4);
                uint32_t so = sw64((uint32_t)(row * 64 + c * 16));
                ldm_x4(ah[mt], bb + 0 * STG_T + so);
                ldm_x4(al[mt], bb + 1 * STG_T + so);
            }
            uint32_t bh[4][2], bl[4][2];
#pragma unroll
            for (int nt = 0; nt < 4; nt++) {
                int row = wn + nt * 8 + (lane & 7);
                int c = ks * 2 + ((lane >> 3) & 1);
                uint32_t so = sw64((uint32_t)(row * 64 + c * 16));
                ldm_x2(bh[nt], bb + 2 * STG_T + so);
                ldm_x2(bl[nt], bb + 3 * STG_T + so);
            }
#pragma unroll
            for (int mt = 0; mt < 4; mt++)
#pragma unroll
                for (int nt = 0; nt < 4; nt++) {
                    mma_bf16(acc[mt][nt], ah[mt], bh[nt]);
                    mma_bf16(acc[mt][nt], ah[mt], bl[nt]);
                    mma_bf16(acc[mt][nt], al[mt], bh[nt]);
                }
        }
        if (++slot == 3) slot = 0;
    }

    const int g = lane >> 2, t = lane & 3;

    if (MODE == 0) {
        // ---- plain fp32 + bias ----
#pragma unroll
        for (int mt = 0; mt < 4; mt++) {
            int r0 = m0 + wm + mt * 16 + g;
#pragma unroll
            for (int nt = 0; nt < 4; nt++) {
                int col = n0 + wn + nt * 8 + t * 2;
                float2 bv = *(const float2*)&bias[col];
                float2 o0, o1;
                o0.x = acc[mt][nt][0] + bv.x;
                o0.y = acc[mt][nt][1] + bv.y;
                o1.x = acc[mt][nt][2] + bv.x;
                o1.y = acc[mt][nt][3] + bv.y;
                *(float2*)&C[(size_t)r0 * DM + col] = o0;
                *(float2*)&C[(size_t)(r0 + 8) * DM + col] = o1;
            }
        }
        return;
    }

    // ---- staged epilogues: tile -> smem fp32 [128][129] (reuse stages) ----
    __syncthreads();                       // all ldmatrix reads done
    float* csm = (float*)smraw;
#pragma unroll
    for (int mt = 0; mt < 4; mt++) {
        int r0 = wm + mt * 16 + g;
#pragma unroll
        for (int nt = 0; nt < 4; nt++) {
            int col = wn + nt * 8 + t * 2;
            float2 bv = *(const float2*)&bias[n0 + col];
            csm[r0 * 129 + col]           = acc[mt][nt][0] + bv.x;
            csm[r0 * 129 + col + 1]       = acc[mt][nt][1] + bv.y;
            csm[(r0 + 8) * 129 + col]     = acc[mt][nt][2] + bv.x;
            csm[(r0 + 8) * 129 + col + 1] = acc[mt][nt][3] + bv.y;
        }
    }
    __syncthreads();

    if (MODE == 1) {
        // ---- Vt: write [(bh*64+d)][s] bf16 hi/lo ----
#pragma unroll
        for (int i = 0; i < 64; i++) {
            int idx = i * 256 + tid;           // 0..16383
            int drow = idx >> 7, scol = idx & 127;
            float v = csm[scol * 129 + drow];
            int m = m0 + scol, b = m >> 11, s = m & (SQ - 1);
            int ncol = n0 + drow, h = ncol >> 6, d = ncol & 63;
            size_t o = (size_t)((b * NH + h) * DKH + d) * SQ + s;
            __nv_bfloat16 hv = __float2bfloat16_rn(v);
            Dhi[o] = hv;
            Dlo[o] = __float2bfloat16_rn(v - __bfloat162float(hv));
        }
    } else {
        // ---- MODE 2: RoPE + (opt) scale + hi/lo split, [m][n] layout ----
        float sc = scaleQ ? 0.125f : 1.0f;
#pragma unroll
        for (int i = 0; i < 64; i++) {
            int idx = i * 256 + tid;           // 0..16383
            int row = idx >> 7, n = idx & 127;
            int d = n & 63, j = d & 31, hb = n & 64;
            float x1 = csm[row * 129 + hb + j];
            float x2 = csm[row * 129 + hb + j + 32];
            int m = m0 + row, s = m & (SQ - 1);
            float2 cs = *(const float2*)&g_rope[2 * (s * 32 + j)];
            float r = (d < 32) ? (x1 * cs.x - x2 * cs.y)
                               : (x1 * cs.y + x2 * cs.x);
            r *= sc;
            __nv_bfloat16 hv = __float2bfloat16_rn(r);
            size_t o = (size_t)m * DM + n0 + n;
            Dhi[o] = hv;
            Dlo[o] = __float2bfloat16_rn(r - __bfloat162float(hv));
        }
    }
}

// ---------------------------------------------------------------------------
// Tensor-core flash attention; epilogue writes bf16 hi/lo (a_hi/a_lo).
// ---------------------------------------------------------------------------
#define FS_QH 0
#define FS_QL 16384
#define FS_ST 32768
#define FS_STB 32768
#define FA3_SMEM (FS_ST + 2 * FS_STB + 1024)

__global__ __launch_bounds__(256, 2) void flash_tc()
{
    extern __shared__ char smraw[];
    const uint32_t sb = (smem_u32(smraw) + 1023) & ~1023u;

    const int tid = threadIdx.x;
    const int wid = tid >> 5, lane = tid & 31;
    const int bh = blockIdx.y, b = bh >> 4, h = bh & 15;
    const int q0 = blockIdx.x * 128;

    const __nv_bfloat16* Qh = g_bf + BF_QHI + (size_t)(b * SQ + q0) * DM + h * DKH;
    const __nv_bfloat16* Ql = g_bf + BF_QLO + (size_t)(b * SQ + q0) * DM + h * DKH;
    const __nv_bfloat16* Kh = g_bf + BF_KHI + (size_t)(b * SQ) * DM + h * DKH;
    const __nv_bfloat16* Kl = g_bf + BF_KLO + (size_t)(b * SQ) * DM + h * DKH;
    const __nv_bfloat16* Vh = g_bf + BF_VTHI + (size_t)(bh * DKH) * SQ;
    const __nv_bfloat16* Vl = g_bf + BF_VTLO + (size_t)(bh * DKH) * SQ;

#pragma unroll
    for (int it = 0; it < 8; it++) {
        int i = it * 256 + tid;            // 0..2047
        int arr = i >> 10, idx = i & 1023;
        int row = idx >> 3, c8 = idx & 7;
        const __nv_bfloat16* src = (arr ? Ql : Qh) + (size_t)row * DM + c8 * 8;
        uint32_t dst = sb + (arr ? FS_QL : FS_QH)
                     + sw128((uint32_t)(row * 128 + c8 * 16));
        cp_async16(dst, src);
    }
    CP_COMMIT();

    auto load_stage = [&](int ktile, int buf) {
        const uint32_t bb = sb + FS_ST + buf * FS_STB;
#pragma unroll
        for (int it = 0; it < 8; it++) {
            int i = it * 256 + tid;        // 0..2047
            int tile = i >> 9, idx = i & 511;
            int row = idx >> 3, c8 = idx & 7;
            const __nv_bfloat16* src;
            if (tile < 2) {
                src = (tile ? Kl : Kh)
                    + (size_t)(ktile * 64 + row) * DM + c8 * 8;
            } else {
                src = ((tile == 3) ? Vl : Vh)
                    + (size_t)row * SQ + ktile * 64 + c8 * 8;
            }
            uint32_t dst = bb + (tile << 13)
                         + sw128((uint32_t)(row * 128 + c8 * 16));
            cp_async16(dst, src);
        }
    };

    load_stage(0, 0);
    CP_COMMIT();
    CP_WAIT(1);                // Q arrived
    __syncthreads();

    uint32_t qh[4][4], ql[4][4];
#pragma unroll
    for (int kt = 0; kt < 4; kt++) {
        int row = wid * 16 + (lane & 15);
        uint32_t so = sw128((uint32_t)(row * 128 + kt * 32 + (lane >> 4) * 16));
        ldm_x4(qh[kt], sb + FS_QH + so);
        ldm_x4(ql[kt], sb + FS_QL + so);
    }

    float m_i[2] = {-1e30f, -1e30f};
    float l_i[2] = {0.f, 0.f};
    float o[8][4];
#pragma unroll
    for (int nt = 0; nt < 8; nt++)
#pragma unroll
        for (int r = 0; r < 4; r++) o[nt][r] = 0.f;

    for (int ktile = 0; ktile < SQ / 64; ktile++) {
        const int buf = ktile & 1;
        if (ktile < SQ / 64 - 1) {
            load_stage(ktile + 1, buf ^ 1);
            CP_COMMIT();
            CP_WAIT(1);
        } else {
            CP_WAIT(0);
        }
        __syncthreads();

        const uint32_t bb = sb + FS_ST + buf * FS_STB;
        const uint32_t KH = bb, KL = bb + 8192, VH = bb + 16384, VL = bb + 24576;

        float sacc[8][4];
#pragma unroll
        for (int nt = 0; nt < 8; nt++)
#pragma unroll
            for (int r = 0; r < 4; r++) sacc[nt][r] = 0.f;

#pragma unroll
        for (int kt = 0; kt < 4; kt++) {
            uint32_t bhf[8][2], blf[8][2];
#pragma unroll
            for (int nt = 0; nt < 8; nt++) {
                int row = nt * 8 + (lane & 7);
                uint32_t so = sw128((uint32_t)(row * 128 + kt * 32
                                               + ((lane >> 3) & 1) * 16));
                ldm_x2(bhf[nt], KH + so);
                ldm_x2(blf[nt], KL + so);
            }
#pragma unroll
            for (int nt = 0; nt < 8; nt++) {
                mma_bf16(sacc[nt], qh[kt], bhf[nt]);
                mma_bf16(sacc[nt], qh[kt], blf[nt]);
                mma_bf16(sacc[nt], ql[kt], bhf[nt]);
            }
        }

        float mx0 = -1e30f, mx1 = -1e30f;
#pragma unroll
        for (int nt = 0; nt < 8; nt++) {
            mx0 = fmaxf(mx0, fmaxf(sacc[nt][0], sacc[nt][1]));
            mx1 = fmaxf(mx1, fmaxf(sacc[nt][2], sacc[nt][3]));
        }
        mx0 = fmaxf(mx0, __shfl_xor_sync(0xffffffffu, mx0, 1));
        mx0 = fmaxf(mx0, __shfl_xor_sync(0xffffffffu, mx0, 2));
        mx1 = fmaxf(mx1, __shfl_xor_sync(0xffffffffu, mx1, 1));
        mx1 = fmaxf(mx1, __shfl_xor_sync(0xffffffffu, mx1, 2));
        float mn0 = fmaxf(m_i[0], mx0), mn1 = fmaxf(m_i[1], mx1);
        float al0 = __expf(m_i[0] - mn0), al1 = __expf(m_i[1] - mn1);
        float rs0 = 0.f, rs1 = 0.f;
#pragma unroll
        for (int nt = 0; nt < 8; nt++) {
            sacc[nt][0] = __expf(sacc[nt][0] - mn0);
            sacc[nt][1] = __expf(sacc[nt][1] - mn0);
            sacc[nt][2] = __expf(sacc[nt][2] - mn1);
            sacc[nt][3] = __expf(sacc[nt][3] - mn1);
            rs0 += sacc[nt][0] + sacc[nt][1];
            rs1 += sacc[nt][2] + sacc[nt][3];
        }
        rs0 += __shfl_xor_sync(0xffffffffu, rs0, 1);
        rs0 += __shfl_xor_sync(0xffffffffu, rs0, 2);
        rs1 += __shfl_xor_sync(0xffffffffu, rs1, 1);
        rs1 += __shfl_xor_sync(0xffffffffu, rs1, 2);
        l_i[0] = l_i[0] * al0 + rs0;
        l_i[1] = l_i[1] * al1 + rs1;
        m_i[0] = mn0; m_i[1] = mn1;
#pragma unroll
        for (int nt = 0; nt < 8; nt++) {
            o[nt][0] *= al0; o[nt][1] *= al0;
            o[nt][2] *= al1; o[nt][3] *= al1;
        }

#pragma unroll
        for (int t = 0; t < 4; t++) {
            float p00 = sacc[2 * t][0], p01 = sacc[2 * t][1];
            float p02 = sacc[2 * t][2], p03 = sacc[2 * t][3];
            float p10 = sacc[2 * t + 1][0], p11 = sacc[2 * t + 1][1];
            float p12 = sacc[2 * t + 1][2], p13 = sacc[2 * t + 1][3];
            float h00 = __bfloat162float(__float2bfloat16_rn(p00));
            float h01 = __bfloat162float(__float2bfloat16_rn(p01));
            float h02 = __bfloat162float(__float2bfloat16_rn(p02));
            float h03 = __bfloat162float(__float2bfloat16_rn(p03));
            float h10 = __bfloat162float(__float2bfloat16_rn(p10));
            float h11 = __bfloat162float(__float2bfloat16_rn(p11));
            float h12 = __bfloat162float(__float2bfloat16_rn(p12));
            float h13 = __bfloat162float(__float2bfloat16_rn(p13));
            uint32_t ahf[4], alf[4];
            ahf[0] = packbf2(h00, h01); ahf[1] = packbf2(h02, h03);
            ahf[2] = packbf2(h10, h11); ahf[3] = packbf2(h12, h13);
            alf[0] = packbf2(p00 - h00, p01 - h01);
            alf[1] = packbf2(p02 - h02, p03 - h03);
            alf[2] = packbf2(p10 - h10, p11 - h11);
            alf[3] = packbf2(p12 - h12, p13 - h13);
#pragma unroll
            for (int nt = 0; nt < 8; nt++) {
                uint32_t vh[2], vl[2];
                int row = nt * 8 + (lane & 7);
                uint32_t so = sw128((uint32_t)(row * 128 + t * 32
                                               + ((lane >> 3) & 1) * 16));
                ldm_x2(vh, VH + so);
                ldm_x2(vl, VL + so);
                mma_bf16(o[nt], ahf, vh);
                mma_bf16(o[nt], ahf, vl);
                mma_bf16(o[nt], alf, vh);
            }
        }
        __syncthreads();
    }

    // ---- epilogue: divide by l, bf16 hi/lo split, store a_hi/a_lo ----
    float inv0 = 1.f / l_i[0], inv1 = 1.f / l_i[1];
    int r0 = q0 + wid * 16 + (lane >> 2);
    __nv_bfloat16* Ah = g_bf + BF_AHI + (size_t)(b * SQ) * DM + h * DKH;
    __nv_bfloat16* Al = g_bf + BF_ALO + (size_t)(b * SQ) * DM + h * DKH;
#pragma unroll
    for (int nt = 0; nt < 8; nt++) {
        int col = nt * 8 + (lane & 3) * 2;
        float a0 = o[nt][0] * inv0, a1 = o[nt][1] * inv0;
        float a2 = o[nt][2] * inv1, a3 = o[nt][3] * inv1;
        float h0 = __bfloat162float(__float2bfloat16_rn(a0));
        float h1 = __bfloat162float(__float2bfloat16_rn(a1));
        float h2 = __bfloat162float(__float2bfloat16_rn(a2));
        float h3 = __bfloat162float(__float2bfloat16_rn(a3));
        *(uint32_t*)&Ah[(size_t)r0 * DM + col]       = packbf2(h0, h1);
        *(uint32_t*)&Al[(size_t)r0 * DM + col]       = packbf2(a0 - h0, a1 - h1);
        *(uint32_t*)&Ah[(size_t)(r0 + 8) * DM + col] = packbf2(h2, h3);
        *(uint32_t*)&Al[(size_t)(r0 + 8) * DM + col] = packbf2(a2 - h2, a3 - h3);
    }
}

// ---------------------------------------------------------------------------
extern "C" void kernel_launch(void* const* d_in, const int* in_sizes, int n_in,
                              void* d_out, int out_size)
{
    const float* x  = (const float*)d_in[0];
    const float* Wq = (const float*)d_in[1];
    const float* bq = (const float*)d_in[2];
    const float* Wk = (const float*)d_in[3];
    const float* bk = (const float*)d_in[4];
    const float* Wv = (const float*)d_in[5];
    const float* bv = (const float*)d_in[6];
    const float* Wo = (const float*)d_in[7];
    const float* bo = (const float*)d_in[8];
    float* out = (float*)d_out;

    __nv_bfloat16* bf = nullptr;
    cudaGetSymbolAddress((void**)&bf, g_bf);

    cudaFuncSetAttribute(mm_gemm<0>,
                         cudaFuncAttributeMaxDynamicSharedMemorySize, MM_SMEM);
    cudaFuncSetAttribute(mm_gemm<1>,
                         cudaFuncAttributeMaxDynamicSharedMemorySize, MM_SMEM);
    cudaFuncSetAttribute(mm_gemm<2>,
                         cudaFuncAttributeMaxDynamicSharedMemorySize, MM_SMEM);
    cudaFuncSetAttribute(flash_tc,
                         cudaFuncAttributeMaxDynamicSharedMemorySize, FA3_SMEM);

    // 1) prep: rope table, x split, weight transpose+split
    rope_table_kernel<<<SQ * 32 / 256, 256>>>();
    split_kernel<<<MROWS * DM / 1024, 256>>>(x, bf + BF_XHI, bf + BF_XLO);
    wsplit_kernel<<<dim3(32, 32, 4), dim3(32, 8)>>>(Wq, Wk, Wv, Wo);

    // 2) Q/K/V projections with fused epilogues
    mm_gemm<2><<<dim3(8, 32), 256, MM_SMEM>>>(
        bf + BF_XHI, bf + BF_XLO,
        bf + BF_WT + 0ull * DM * DM, bf + BF_WT + 1ull * DM * DM, bq,
        nullptr, bf + BF_QHI, bf + BF_QLO, 1);
    mm_gemm<2><<<dim3(8, 32), 256, MM_SMEM>>>(
        bf + BF_XHI, bf + BF_XLO,
        bf + BF_WT + 2ull * DM * DM, bf + BF_WT + 3ull * DM * DM, bk,
        nullptr, bf + BF_KHI, bf + BF_KLO, 0);
    mm_gemm<1><<<dim3(8, 32), 256, MM_SMEM>>>(
        bf + BF_XHI, bf + BF_XLO,
        bf + BF_WT + 4ull * DM * DM, bf + BF_WT + 5ull * DM * DM, bv,
        nullptr, bf + BF_VTHI, bf + BF_VTLO, 0);

    // 3) Flash attention (writes a_hi/a_lo bf16 directly)
    flash_tc<<<dim3(SQ / 128, NB * NH), 256, FA3_SMEM>>>();

    // 4) output projection (fp32 out)
    mm_gemm<0><<<dim3(8, 32), 256, MM_SMEM>>>(
        bf + BF_AHI, bf + BF_ALO,
        bf + BF_WT + 6ull * DM * DM, bf + BF_WT + 7ull * DM * DM, bo,
        out, nullptr, nullptr, 0);
}

// round 10
// speedup vs baseline: 1.0382x; 1.0382x over previous
#include <cuda_runtime.h>
#include <cuda_bf16.h>
#include <math.h>
#include <stdint.h>

#define SQ   2048
#define NB   2
#define NH   16
#define DKH  64
#define DM   1024
#define MROWS 4096   // NB*SQ

// ---------------------------------------------------------------------------
// Scratch (__device__ globals; allocation-free rule)
// ---------------------------------------------------------------------------
__device__ float g_rope[SQ * 32 * 2];                    // cos,sin per (s,j)

// bf16 scratch offsets (elements; MROWS*DM = 4M, DM*DM = 1M)
#define BF_XHI  0ull
#define BF_XLO  (1ull * MROWS * DM)
#define BF_WT   (2ull * MROWS * DM)                       // 8 x DM*DM
#define BF_AHI  (BF_WT + 8ull * DM * DM)
#define BF_ALO  (BF_AHI + 1ull * MROWS * DM)
#define BF_QHI  (BF_ALO + 1ull * MROWS * DM)
#define BF_QLO  (BF_QHI + 1ull * MROWS * DM)
#define BF_KHI  (BF_QLO + 1ull * MROWS * DM)
#define BF_KLO  (BF_KHI + 1ull * MROWS * DM)
#define BF_VTHI (BF_KLO + 1ull * MROWS * DM)
#define BF_VTLO (BF_VTHI + 1ull * MROWS * DM)
__device__ __nv_bfloat16 g_bf[BF_VTLO + 1ull * MROWS * DM];

// ---------------------------------------------------------------------------
// Helpers (sm_100-safe: cp.async, ldmatrix, mma.sync only)
// ---------------------------------------------------------------------------
__device__ __forceinline__ uint32_t smem_u32(const void* p) {
    uint32_t a;
    asm("{ .reg .u64 t; cvta.to.shared.u64 t, %1; cvt.u32.u64 %0, t; }"
        : "=r"(a) : "l"(p));
    return a;
}

__device__ __forceinline__ uint32_t sw64(uint32_t off) {
    return off ^ ((off >> 3) & 0x30);
}
__device__ __forceinline__ uint32_t sw128(uint32_t off) {
    return off ^ ((off >> 3) & 0x70);
}

__device__ __forceinline__ void ldm_x4(uint32_t* r, uint32_t addr) {
    asm volatile("ldmatrix.sync.aligned.m8n8.x4.shared.b16 {%0,%1,%2,%3}, [%4];"
                 : "=r"(r[0]), "=r"(r[1]), "=r"(r[2]), "=r"(r[3]) : "r"(addr));
}
__device__ __forceinline__ void ldm_x2(uint32_t* r, uint32_t addr) {
    asm volatile("ldmatrix.sync.aligned.m8n8.x2.shared.b16 {%0,%1}, [%2];"
                 : "=r"(r[0]), "=r"(r[1]) : "r"(addr));
}

__device__ __forceinline__ void mma_bf16(float* d, const uint32_t* a,
                                         const uint32_t* b) {
    asm volatile(
        "mma.sync.aligned.m16n8k16.row.col.f32.bf16.bf16.f32 "
        "{%0,%1,%2,%3}, {%4,%5,%6,%7}, {%8,%9}, {%0,%1,%2,%3};"
        : "+f"(d[0]), "+f"(d[1]), "+f"(d[2]), "+f"(d[3])
        : "r"(a[0]), "r"(a[1]), "r"(a[2]), "r"(a[3]), "r"(b[0]), "r"(b[1]));
}

__device__ __forceinline__ void cp_async16(uint32_t dst, const void* src) {
    asm volatile("cp.async.cg.shared.global [%0], [%1], 16;"
                 :: "r"(dst), "l"(src));
}
#define CP_COMMIT() asm volatile("cp.async.commit_group;" ::: "memory")
#define CP_WAIT(n)  asm volatile("cp.async.wait_group %0;" :: "n"(n) : "memory")

__device__ __forceinline__ uint32_t packbf2(float a, float b) {
    __nv_bfloat162 t = __floats2bfloat162_rn(a, b);
    return *(uint32_t*)&t;
}

// ---------------------------------------------------------------------------
// Prep: fp32 -> (bf16 hi, bf16 lo) split, 4 elems/thread
// ---------------------------------------------------------------------------
__global__ __launch_bounds__(256) void split_kernel(
    const float* __restrict__ src, __nv_bfloat16* __restrict__ hi,
    __nv_bfloat16* __restrict__ lo)
{
    size_t i = (size_t)(blockIdx.x * 256 + threadIdx.x) * 4;
    float4 v = *(const float4*)(src + i);
    __nv_bfloat16 h0 = __float2bfloat16_rn(v.x);
    __nv_bfloat16 h1 = __float2bfloat16_rn(v.y);
    __nv_bfloat16 h2 = __float2bfloat16_rn(v.z);
    __nv_bfloat16 h3 = __float2bfloat16_rn(v.w);
    __nv_bfloat16 l0 = __float2bfloat16_rn(v.x - __bfloat162float(h0));
    __nv_bfloat16 l1 = __float2bfloat16_rn(v.y - __bfloat162float(h1));
    __nv_bfloat16 l2 = __float2bfloat16_rn(v.z - __bfloat162float(h2));
    __nv_bfloat16 l3 = __float2bfloat16_rn(v.w - __bfloat162float(h3));
    ((__nv_bfloat162*)(hi + i))[0] = __nv_bfloat162(h0, h1);
    ((__nv_bfloat162*)(hi + i))[1] = __nv_bfloat162(h2, h3);
    ((__nv_bfloat162*)(lo + i))[0] = __nv_bfloat162(l0, l1);
    ((__nv_bfloat162*)(lo + i))[1] = __nv_bfloat162(l2, l3);
}

// ---------------------------------------------------------------------------
// Prep: transpose + split the 4 weight matrices W[k][n] -> Wt_hi/lo[n][k]
// ---------------------------------------------------------------------------
__global__ __launch_bounds__(256) void wsplit_kernel(
    const float* __restrict__ W0, const float* __restrict__ W1,
    const float* __restrict__ W2, const float* __restrict__ W3)
{
    __shared__ float t[32][33];
    const float* W = (blockIdx.z == 0) ? W0 : (blockIdx.z == 1) ? W1
                   : (blockIdx.z == 2) ? W2 : W3;
    __nv_bfloat16* whi = g_bf + BF_WT + (size_t)(2 * blockIdx.z) * DM * DM;
    __nv_bfloat16* wlo = whi + (size_t)DM * DM;
    int tx = threadIdx.x, ty = threadIdx.y;
    int n = blockIdx.x * 32 + tx;
#pragma unroll
    for (int i = 0; i < 32; i += 8)
        t[ty + i][tx] = W[(size_t)(blockIdx.y * 32 + ty + i) * DM + n];
    __syncthreads();
#pragma unroll
    for (int i = 0; i < 32; i += 8) {
        float v = t[tx][ty + i];
        __nv_bfloat16 h = __float2bfloat16_rn(v);
        __nv_bfloat16 l = __float2bfloat16_rn(v - __bfloat162float(h));
        size_t o = (size_t)(blockIdx.x * 32 + ty + i) * DM + blockIdx.y * 32 + tx;
        whi[o] = h;
        wlo[o] = l;
    }
}

// ---------------------------------------------------------------------------
// RoPE cos/sin table: (s, j) -> g_rope[2*(s*32+j)] = {cos, sin}
// ---------------------------------------------------------------------------
__global__ __launch_bounds__(256) void rope_table_kernel()
{
    int i = blockIdx.x * 256 + threadIdx.x;   // 0 .. 65535
    int s = i >> 5, j = i & 31;
    float invf = (float)pow(10000.0, -(double)j / 32.0);
    float ang = (float)s * invf;
    float sn, c;
    sincosf(ang, &sn, &c);
    g_rope[2 * i]     = c;
    g_rope[2 * i + 1] = sn;
}

// ---------------------------------------------------------------------------
// mma.sync bf16-split GEMM, 3-stage cp.async pipeline, fused epilogues.
// MODE 0: C = acc + bias (fp32, row-major)
// MODE 1: Vt hi/lo bf16, transposed write [(bh*64+d)][s]  (vectorized x4)
// MODE 2: RoPE (table) + opt 0.125 scale + bf16 hi/lo split (vectorized x4)
// ---------------------------------------------------------------------------
#define KCH 32
#define NKT (DM / KCH)             // 32 chunks
#define STG_T 8192
#define STG_B (4 * STG_T)          // 32 KB per stage
#define MM_SMEM (3 * STG_B + 1024)

template <int MODE>
__global__ __launch_bounds__(256, 2) void mm_gemm(
    const __nv_bfloat16* __restrict__ Ahi, const __nv_bfloat16* __restrict__ Alo,
    const __nv_bfloat16* __restrict__ Bhi, const __nv_bfloat16* __restrict__ Blo,
    const float* __restrict__ bias, float* __restrict__ C,
    __nv_bfloat16* __restrict__ Dhi, __nv_bfloat16* __restrict__ Dlo,
    int scaleQ)
{
    extern __shared__ char smraw[];
    const uint32_t sbase = (smem_u32(smraw) + 1023) & ~1023u;

    const int tid  = threadIdx.x;
    const int wid  = tid >> 5, lane = tid & 31;
    const int m0   = blockIdx.y * 128, n0 = blockIdx.x * 128;
    const int wm   = (wid >> 2) * 64, wn = (wid & 3) * 32;

    float acc[4][4][4];
#pragma unroll
    for (int i = 0; i < 4; i++)
#pragma unroll
        for (int j = 0; j < 4; j++)
#pragma unroll
            for (int r = 0; r < 4; r++) acc[i][j][r] = 0.f;

    auto load_stage = [&](int kt, int slot) {
        const uint32_t bb = sbase + slot * STG_B;
#pragma unroll
        for (int it = 0; it < 8; it++) {
            int i = it * 256 + tid;
            int tile = i >> 9, idx = i & 511;
            int r = idx >> 2, c = idx & 3;
            uint32_t dst = bb + tile * STG_T + sw64((uint32_t)(r * 64 + c * 16));
            size_t off = (tile < 2)
                ? (size_t)(m0 + r) * DM + kt * KCH + c * 8
                : (size_t)(n0 + r) * DM + kt * KCH + c * 8;
            const __nv_bfloat16* src =
                (tile == 0) ? Ahi + off : (tile == 1) ? Alo + off
              : (tile == 2) ? Bhi + off : Blo + off;
            cp_async16(dst, src);
        }
    };

    load_stage(0, 0); CP_COMMIT();
    load_stage(1, 1); CP_COMMIT();

    int slot = 0;
    for (int kt = 0; kt < NKT; kt++) {
        CP_WAIT(1);
        __syncthreads();
        if (kt + 2 < NKT) {
            int ns = slot + 2; if (ns >= 3) ns -= 3;
            load_stage(kt + 2, ns);
            CP_COMMIT();
        } else {
            CP_COMMIT();
        }

        const uint32_t bb = sbase + slot * STG_B;
#pragma unroll
        for (int ks = 0; ks < 2; ks++) {
            uint32_t ah[4][4], al[4][4];
#pragma unroll
            for (int mt = 0; mt < 4; mt++) {
                int row = wm + mt * 16 + (lane & 15);
                int c = ks * 2 + (lane >> 4);
                uint32_t so = sw64((uint32_t)(row * 64 + c * 16));
                ldm_x4(ah[mt], bb + 0 * STG_T + so);
                ldm_x4(al[mt], bb + 1 * STG_T + so);
            }
            uint32_t bh[4][2], bl[4][2];
#pragma unroll
            for (int nt = 0; nt < 4; nt++) {
                int row = wn + nt * 8 + (lane & 7);
                int c = ks * 2 + ((lane >> 3) & 1);
                uint32_t so = sw64((uint32_t)(row * 64 + c * 16));
                ldm_x2(bh[nt], bb + 2 * STG_T + so);
                ldm_x2(bl[nt], bb + 3 * STG_T + so);
            }
#pragma unroll
            for (int mt = 0; mt < 4; mt++)
#pragma unroll
                for (int nt = 0; nt < 4; nt++) {
                    mma_bf16(acc[mt][nt], ah[mt], bh[nt]);
                    mma_bf16(acc[mt][nt], ah[mt], bl[nt]);
                    mma_bf16(acc[mt][nt], al[mt], bh[nt]);
                }
        }
        if (++slot == 3) slot = 0;
    }

    const int g = lane >> 2, t = lane & 3;

    if (MODE == 0) {
        // ---- plain fp32 + bias ----
#pragma unroll
        for (int mt = 0; mt < 4; mt++) {
            int r0 = m0 + wm + mt * 16 + g;
#pragma unroll
            for (int nt = 0; nt < 4; nt++) {
                int col = n0 + wn + nt * 8 + t * 2;
                float2 bv = *(const float2*)&bias[col];
                float2 o0, o1;
                o0.x = acc[mt][nt][0] + bv.x;
                o0.y = acc[mt][nt][1] + bv.y;
                o1.x = acc[mt][nt][2] + bv.x;
                o1.y = acc[mt][nt][3] + bv.y;
                *(float2*)&C[(size_t)r0 * DM + col] = o0;
                *(float2*)&C[(size_t)(r0 + 8) * DM + col] = o1;
            }
        }
        return;
    }

    // ---- staged epilogues: tile -> smem fp32 [128][129] (reuse stages) ----
    __syncthreads();                       // all ldmatrix reads done
    float* csm = (float*)smraw;
#pragma unroll
    for (int mt = 0; mt < 4; mt++) {
        int r0 = wm + mt * 16 + g;
#pragma unroll
        for (int nt = 0; nt < 4; nt++) {
            int col = wn + nt * 8 + t * 2;
            float2 bv = *(const float2*)&bias[n0 + col];
            csm[r0 * 129 + col]           = acc[mt][nt][0] + bv.x;
            csm[r0 * 129 + col + 1]       = acc[mt][nt][1] + bv.y;
            csm[(r0 + 8) * 129 + col]     = acc[mt][nt][2] + bv.x;
            csm[(r0 + 8) * 129 + col + 1] = acc[mt][nt][3] + bv.y;
        }
    }
    __syncthreads();

    if (MODE == 1) {
        // ---- Vt: [(bh*64+d)][s] bf16 hi/lo, 4 consecutive s per thread ----
#pragma unroll
        for (int i = 0; i < 16; i++) {
            int idx = i * 256 + tid;           // 0..4095 (chunks of 4 s)
            int drow = idx >> 5, s4 = (idx & 31) * 4;
            float v0 = csm[(s4 + 0) * 129 + drow];
            float v1 = csm[(s4 + 1) * 129 + drow];
            float v2 = csm[(s4 + 2) * 129 + drow];
            float v3 = csm[(s4 + 3) * 129 + drow];
            int m = m0 + s4, b = m >> 11, s = m & (SQ - 1);
            int ncol = n0 + drow, h = ncol >> 6, d = ncol & 63;
            size_t o = (size_t)((b * NH + h) * DKH + d) * SQ + s;
            float h0 = __bfloat162float(__float2bfloat16_rn(v0));
            float h1 = __bfloat162float(__float2bfloat16_rn(v1));
            float h2 = __bfloat162float(__float2bfloat16_rn(v2));
            float h3 = __bfloat162float(__float2bfloat16_rn(v3));
            uint2 hv, lv;
            hv.x = packbf2(h0, h1); hv.y = packbf2(h2, h3);
            lv.x = packbf2(v0 - h0, v1 - h1);
            lv.y = packbf2(v2 - h2, v3 - h3);
            *(uint2*)&Dhi[o] = hv;
            *(uint2*)&Dlo[o] = lv;
        }
    } else {
        // ---- MODE 2: RoPE + (opt) scale + hi/lo split, 4 n per thread ----
        float sc = scaleQ ? 0.125f : 1.0f;
#pragma unroll
        for (int i = 0; i < 16; i++) {
            int idx = i * 256 + tid;           // 0..4095 (chunks of 4 n)
            int row = idx >> 5, n4 = (idx & 31) * 4;
            int d = n4 & 63, j = d & 31, hb = n4 & 64;
            int m = m0 + row, s = m & (SQ - 1);
            const float* cr = csm + row * 129 + hb;
            float r[4];
            bool first = (d < 32);
#pragma unroll
            for (int e = 0; e < 4; e++) {
                int jj = j + e;
                float x1 = cr[jj], x2 = cr[jj + 32];
                float2 cs = *(const float2*)&g_rope[2 * (s * 32 + jj)];
                r[e] = first ? (x1 * cs.x - x2 * cs.y)
                             : (x1 * cs.y + x2 * cs.x);
                r[e] *= sc;
            }
            float h0 = __bfloat162float(__float2bfloat16_rn(r[0]));
            float h1 = __bfloat162float(__float2bfloat16_rn(r[1]));
            float h2 = __bfloat162float(__float2bfloat16_rn(r[2]));
            float h3 = __bfloat162float(__float2bfloat16_rn(r[3]));
            uint2 hv, lv;
            hv.x = packbf2(h0, h1); hv.y = packbf2(h2, h3);
            lv.x = packbf2(r[0] - h0, r[1] - h1);
            lv.y = packbf2(r[2] - h2, r[3] - h3);
            size_t o = (size_t)m * DM + n0 + n4;
            *(uint2*)&Dhi[o] = hv;
            *(uint2*)&Dlo[o] = lv;
        }
    }
}

// ---------------------------------------------------------------------------
// Tensor-core flash attention; epilogue writes bf16 hi/lo (a_hi/a_lo).
// ---------------------------------------------------------------------------
#define FS_QH 0
#define FS_QL 16384
#define FS_ST 32768
#define FS_STB 32768
#define FA3_SMEM (FS_ST + 2 * FS_STB + 1024)

__global__ __launch_bounds__(256, 2) void flash_tc()
{
    extern __shared__ char smraw[];
    const uint32_t sb = (smem_u32(smraw) + 1023) & ~1023u;

    const int tid = threadIdx.x;
    const int wid = tid >> 5, lane = tid & 31;
    const int bh = blockIdx.y, b = bh >> 4, h = bh & 15;
    const int q0 = blockIdx.x * 128;

    const __nv_bfloat16* Qh = g_bf + BF_QHI + (size_t)(b * SQ + q0) * DM + h * DKH;
    const __nv_bfloat16* Ql = g_bf + BF_QLO + (size_t)(b * SQ + q0) * DM + h * DKH;
    const __nv_bfloat16* Kh = g_bf + BF_KHI + (size_t)(b * SQ) * DM + h * DKH;
    const __nv_bfloat16* Kl = g_bf + BF_KLO + (size_t)(b * SQ) * DM + h * DKH;
    const __nv_bfloat16* Vh = g_bf + BF_VTHI + (size_t)(bh * DKH) * SQ;
    const __nv_bfloat16* Vl = g_bf + BF_VTLO + (size_t)(bh * DKH) * SQ;

#pragma unroll
    for (int it = 0; it < 8; it++) {
        int i = it * 256 + tid;            // 0..2047
        int arr = i >> 10, idx = i & 1023;
        int row = idx >> 3, c8 = idx & 7;
        const __nv_bfloat16* src = (arr ? Ql : Qh) + (size_t)row * DM + c8 * 8;
        uint32_t dst = sb + (arr ? FS_QL : FS_QH)
                     + sw128((uint32_t)(row * 128 + c8 * 16));
        cp_async16(dst, src);
    }
    CP_COMMIT();

    auto load_stage = [&](int ktile, int buf) {
        const uint32_t bb = sb + FS_ST + buf * FS_STB;
#pragma unroll
        for (int it = 0; it < 8; it++) {
            int i = it * 256 + tid;        // 0..2047
            int tile = i >> 9, idx = i & 511;
            int row = idx >> 3, c8 = idx & 7;
            const __nv_bfloat16* src;
            if (tile < 2) {
                src = (tile ? Kl : Kh)
                    + (size_t)(ktile * 64 + row) * DM + c8 * 8;
            } else {
                src = ((tile == 3) ? Vl : Vh)
                    + (size_t)row * SQ + ktile * 64 + c8 * 8;
            }
            uint32_t dst = bb + (tile << 13)
                         + sw128((uint32_t)(row * 128 + c8 * 16));
            cp_async16(dst, src);
        }
    };

    load_stage(0, 0);
    CP_COMMIT();
    CP_WAIT(1);                // Q arrived
    __syncthreads();

    uint32_t qh[4][4], ql[4][4];
#pragma unroll
    for (int kt = 0; kt < 4; kt++) {
        int row = wid * 16 + (lane & 15);
        uint32_t so = sw128((uint32_t)(row * 128 + kt * 32 + (lane >> 4) * 16));
        ldm_x4(qh[kt], sb + FS_QH + so);
        ldm_x4(ql[kt], sb + FS_QL + so);
    }

    float m_i[2] = {-1e30f, -1e30f};
    float l_i[2] = {0.f, 0.f};
    float o[8][4];
#pragma unroll
    for (int nt = 0; nt < 8; nt++)
#pragma unroll
        for (int r = 0; r < 4; r++) o[nt][r] = 0.f;

    for (int ktile = 0; ktile < SQ / 64; ktile++) {
        const int buf = ktile & 1;
        if (ktile < SQ / 64 - 1) {
            load_stage(ktile + 1, buf ^ 1);
            CP_COMMIT();
            CP_WAIT(1);
        } else {
            CP_WAIT(0);
        }
        __syncthreads();

        const uint32_t bb = sb + FS_ST + buf * FS_STB;
        const uint32_t KH = bb, KL = bb + 8192, VH = bb + 16384, VL = bb + 24576;

        float sacc[8][4];
#pragma unroll
        for (int nt = 0; nt < 8; nt++)
#pragma unroll
            for (int r = 0; r < 4; r++) sacc[nt][r] = 0.f;

#pragma unroll
        for (int kt = 0; kt < 4; kt++) {
            uint32_t bhf[8][2], blf[8][2];
#pragma unroll
            for (int nt = 0; nt < 8; nt++) {
                int row = nt * 8 + (lane & 7);
                uint32_t so = sw128((uint32_t)(row * 128 + kt * 32
                                               + ((lane >> 3) & 1) * 16));
                ldm_x2(bhf[nt], KH + so);
                ldm_x2(blf[nt], KL + so);
            }
#pragma unroll
            for (int nt = 0; nt < 8; nt++) {
                mma_bf16(sacc[nt], qh[kt], bhf[nt]);
                mma_bf16(sacc[nt], qh[kt], blf[nt]);
                mma_bf16(sacc[nt], ql[kt], bhf[nt]);
            }
        }

        float mx0 = -1e30f, mx1 = -1e30f;
#pragma unroll
        for (int nt = 0; nt < 8; nt++) {
            mx0 = fmaxf(mx0, fmaxf(sacc[nt][0], sacc[nt][1]));
            mx1 = fmaxf(mx1, fmaxf(sacc[nt][2], sacc[nt][3]));
        }
        mx0 = fmaxf(mx0, __shfl_xor_sync(0xffffffffu, mx0, 1));
        mx0 = fmaxf(mx0, __shfl_xor_sync(0xffffffffu, mx0, 2));
        mx1 = fmaxf(mx1, __shfl_xor_sync(0xffffffffu, mx1, 1));
        mx1 = fmaxf(mx1, __shfl_xor_sync(0xffffffffu, mx1, 2));
        float mn0 = fmaxf(m_i[0], mx0), mn1 = fmaxf(m_i[1], mx1);
        float al0 = __expf(m_i[0] - mn0), al1 = __expf(m_i[1] - mn1);
        float rs0 = 0.f, rs1 = 0.f;
#pragma unroll
        for (int nt = 0; nt < 8; nt++) {
            sacc[nt][0] = __expf(sacc[nt][0] - mn0);
            sacc[nt][1] = __expf(sacc[nt][1] - mn0);
            sacc[nt][2] = __expf(sacc[nt][2] - mn1);
            sacc[nt][3] = __expf(sacc[nt][3] - mn1);
            rs0 += sacc[nt][0] + sacc[nt][1];
            rs1 += sacc[nt][2] + sacc[nt][3];
        }
        rs0 += __shfl_xor_sync(0xffffffffu, rs0, 1);
        rs0 += __shfl_xor_sync(0xffffffffu, rs0, 2);
        rs1 += __shfl_xor_sync(0xffffffffu, rs1, 1);
        rs1 += __shfl_xor_sync(0xffffffffu, rs1, 2);
        l_i[0] = l_i[0] * al0 + rs0;
        l_i[1] = l_i[1] * al1 + rs1;
        m_i[0] = mn0; m_i[1] = mn1;
#pragma unroll
        for (int nt = 0; nt < 8; nt++) {
            o[nt][0] *= al0; o[nt][1] *= al0;
            o[nt][2] *= al1; o[nt][3] *= al1;
        }

#pragma unroll
        for (int t = 0; t < 4; t++) {
            float p00 = sacc[2 * t][0], p01 = sacc[2 * t][1];
            float p02 = sacc[2 * t][2], p03 = sacc[2 * t][3];
            float p10 = sacc[2 * t + 1][0], p11 = sacc[2 * t + 1][1];
            float p12 = sacc[2 * t + 1][2], p13 = sacc[2 * t + 1][3];
            float h00 = __bfloat162float(__float2bfloat16_rn(p00));
            float h01 = __bfloat162float(__float2bfloat16_rn(p01));
            float h02 = __bfloat162float(__float2bfloat16_rn(p02));
            float h03 = __bfloat162float(__float2bfloat16_rn(p03));
            float h10 = __bfloat162float(__float2bfloat16_rn(p10));
            float h11 = __bfloat162float(__float2bfloat16_rn(p11));
            float h12 = __bfloat162float(__float2bfloat16_rn(p12));
            float h13 = __bfloat162float(__float2bfloat16_rn(p13));
            uint32_t ahf[4], alf[4];
            ahf[0] = packbf2(h00, h01); ahf[1] = packbf2(h02, h03);
            ahf[2] = packbf2(h10, h11); ahf[3] = packbf2(h12, h13);
            alf[0] = packbf2(p00 - h00, p01 - h01);
            alf[1] = packbf2(p02 - h02, p03 - h03);
            alf[2] = packbf2(p10 - h10, p11 - h11);
            alf[3] = packbf2(p12 - h12, p13 - h13);
#pragma unroll
            for (int nt = 0; nt < 8; nt++) {
                uint32_t vh[2], vl[2];
                int row = nt * 8 + (lane & 7);
                uint32_t so = sw128((uint32_t)(row * 128 + t * 32
                                               + ((lane >> 3) & 1) * 16));
                ldm_x2(vh, VH + so);
                ldm_x2(vl, VL + so);
                mma_bf16(o[nt], ahf, vh);
                mma_bf16(o[nt], ahf, vl);
                mma_bf16(o[nt], alf, vh);
            }
        }
        __syncthreads();
    }

    // ---- epilogue: divide by l, bf16 hi/lo split, store a_hi/a_lo ----
    float inv0 = 1.f / l_i[0], inv1 = 1.f / l_i[1];
    int r0 = q0 + wid * 16 + (lane >> 2);
    __nv_bfloat16* Ah = g_bf + BF_AHI + (size_t)(b * SQ) * DM + h * DKH;
    __nv_bfloat16* Al = g_bf + BF_ALO + (size_t)(b * SQ) * DM + h * DKH;
#pragma unroll
    for (int nt = 0; nt < 8; nt++) {
        int col = nt * 8 + (lane & 3) * 2;
        float a0 = o[nt][0] * inv0, a1 = o[nt][1] * inv0;
        float a2 = o[nt][2] * inv1, a3 = o[nt][3] * inv1;
        float h0 = __bfloat162float(__float2bfloat16_rn(a0));
        float h1 = __bfloat162float(__float2bfloat16_rn(a1));
        float h2 = __bfloat162float(__float2bfloat16_rn(a2));
        float h3 = __bfloat162float(__float2bfloat16_rn(a3));
        *(uint32_t*)&Ah[(size_t)r0 * DM + col]       = packbf2(h0, h1);
        *(uint32_t*)&Al[(size_t)r0 * DM + col]       = packbf2(a0 - h0, a1 - h1);
        *(uint32_t*)&Ah[(size_t)(r0 + 8) * DM + col] = packbf2(h2, h3);
        *(uint32_t*)&Al[(size_t)(r0 + 8) * DM + col] = packbf2(a2 - h2, a3 - h3);
    }
}

// ---------------------------------------------------------------------------
extern "C" void kernel_launch(void* const* d_in, const int* in_sizes, int n_in,
                              void* d_out, int out_size)
{
    const float* x  = (const float*)d_in[0];
    const float* Wq = (const float*)d_in[1];
    const float* bq = (const float*)d_in[2];
    const float* Wk = (const float*)d_in[3];
    const float* bk = (const float*)d_in[4];
    const float* Wv = (const float*)d_in[5];
    const float* bv = (const float*)d_in[6];
    const float* Wo = (const float*)d_in[7];
    const float* bo = (const float*)d_in[8];
    float* out = (float*)d_out;

    __nv_bfloat16* bf = nullptr;
    cudaGetSymbolAddress((void**)&bf, g_bf);

    cudaFuncSetAttribute(mm_gemm<0>,
                         cudaFuncAttributeMaxDynamicSharedMemorySize, MM_SMEM);
    cudaFuncSetAttribute(mm_gemm<1>,
                         cudaFuncAttributeMaxDynamicSharedMemorySize, MM_SMEM);
    cudaFuncSetAttribute(mm_gemm<2>,
                         cudaFuncAttributeMaxDynamicSharedMemorySize, MM_SMEM);
    cudaFuncSetAttribute(flash_tc,
                         cudaFuncAttributeMaxDynamicSharedMemorySize, FA3_SMEM);

    // 1) prep: rope table, x split, weight transpose+split
    rope_table_kernel<<<SQ * 32 / 256, 256>>>();
    split_kernel<<<MROWS * DM / 1024, 256>>>(x, bf + BF_XHI, bf + BF_XLO);
    wsplit_kernel<<<dim3(32, 32, 4), dim3(32, 8)>>>(Wq, Wk, Wv, Wo);

    // 2) Q/K/V projections with fused (vectorized) epilogues
    mm_gemm<2><<<dim3(8, 32), 256, MM_SMEM>>>(
        bf + BF_XHI, bf + BF_XLO,
        bf + BF_WT + 0ull * DM * DM, bf + BF_WT + 1ull * DM * DM, bq,
        nullptr, bf + BF_QHI, bf + BF_QLO, 1);
    mm_gemm<2><<<dim3(8, 32), 256, MM_SMEM>>>(
        bf + BF_XHI, bf + BF_XLO,
        bf + BF_WT + 2ull * DM * DM, bf + BF_WT + 3ull * DM * DM, bk,
        nullptr, bf + BF_KHI, bf + BF_KLO, 0);
    mm_gemm<1><<<dim3(8, 32), 256, MM_SMEM>>>(
        bf + BF_XHI, bf + BF_XLO,
        bf + BF_WT + 4ull * DM * DM, bf + BF_WT + 5ull * DM * DM, bv,
        nullptr, bf + BF_VTHI, bf + BF_VTLO, 0);

    // 3) Flash attention (writes a_hi/a_lo bf16 directly)
    flash_tc<<<dim3(SQ / 128, NB * NH), 256, FA3_SMEM>>>();

    // 4) output projection (fp32 out)
    mm_gemm<0><<<dim3(8, 32), 256, MM_SMEM>>>(
        bf + BF_AHI, bf + BF_ALO,
        bf + BF_WT + 6ull * DM * DM, bf + BF_WT + 7ull * DM * DM, bo,
        out, nullptr, nullptr, 0);
}

// round 12
// speedup vs baseline: 1.0886x; 1.0485x over previous
#include <cuda_runtime.h>
#include <cuda_bf16.h>
#include <math.h>
#include <stdint.h>

#define SQ   2048
#define NB   2
#define NH   16
#define DKH  64
#define DM   1024
#define MROWS 4096   // NB*SQ

// ---------------------------------------------------------------------------
// Scratch (__device__ globals; allocation-free rule)
// ---------------------------------------------------------------------------
__device__ float g_rope[SQ * 32 * 2];                    // cos,sin per (s,j)

// bf16 scratch offsets (elements; MROWS*DM = 4M, DM*DM = 1M)
#define BF_XHI  0ull
#define BF_XLO  (1ull * MROWS * DM)
#define BF_WT   (2ull * MROWS * DM)                       // 8 x DM*DM
#define BF_AHI  (BF_WT + 8ull * DM * DM)
#define BF_ALO  (BF_AHI + 1ull * MROWS * DM)
#define BF_QHI  (BF_ALO + 1ull * MROWS * DM)
#define BF_QLO  (BF_QHI + 1ull * MROWS * DM)
#define BF_KHI  (BF_QLO + 1ull * MROWS * DM)
#define BF_KLO  (BF_KHI + 1ull * MROWS * DM)
#define BF_VTHI (BF_KLO + 1ull * MROWS * DM)
#define BF_VTLO (BF_VTHI + 1ull * MROWS * DM)
__device__ __nv_bfloat16 g_bf[BF_VTLO + 1ull * MROWS * DM];

// ---------------------------------------------------------------------------
// Helpers (sm_100-safe: cp.async, ldmatrix, mma.sync only)
// ---------------------------------------------------------------------------
__device__ __forceinline__ uint32_t smem_u32(const void* p) {
    uint32_t a;
    asm("{ .reg .u64 t; cvta.to.shared.u64 t, %1; cvt.u32.u64 %0, t; }"
        : "=r"(a) : "l"(p));
    return a;
}

__device__ __forceinline__ uint32_t sw64(uint32_t off) {
    return off ^ ((off >> 3) & 0x30);
}
__device__ __forceinline__ uint32_t sw128(uint32_t off) {
    return off ^ ((off >> 3) & 0x70);
}

__device__ __forceinline__ void ldm_x4(uint32_t* r, uint32_t addr) {
    asm volatile("ldmatrix.sync.aligned.m8n8.x4.shared.b16 {%0,%1,%2,%3}, [%4];"
                 : "=r"(r[0]), "=r"(r[1]), "=r"(r[2]), "=r"(r[3]) : "r"(addr));
}

__device__ __forceinline__ void mma_bf16(float* d, const uint32_t* a,
                                         const uint32_t* b) {
    asm volatile(
        "mma.sync.aligned.m16n8k16.row.col.f32.bf16.bf16.f32 "
        "{%0,%1,%2,%3}, {%4,%5,%6,%7}, {%8,%9}, {%0,%1,%2,%3};"
        : "+f"(d[0]), "+f"(d[1]), "+f"(d[2]), "+f"(d[3])
        : "r"(a[0]), "r"(a[1]), "r"(a[2]), "r"(a[3]), "r"(b[0]), "r"(b[1]));
}

__device__ __forceinline__ void cp_async16(uint32_t dst, const void* src) {
    asm volatile("cp.async.cg.shared.global [%0], [%1], 16;"
                 :: "r"(dst), "l"(src));
}
#define CP_COMMIT() asm volatile("cp.async.commit_group;" ::: "memory")
#define CP_WAIT(n)  asm volatile("cp.async.wait_group %0;" :: "n"(n) : "memory")

__device__ __forceinline__ uint32_t packbf2(float a, float b) {
    __nv_bfloat162 t = __floats2bfloat162_rn(a, b);
    return *(uint32_t*)&t;
}

// ---------------------------------------------------------------------------
// Prep: fp32 -> (bf16 hi, bf16 lo) split, 4 elems/thread
// ---------------------------------------------------------------------------
__global__ __launch_bounds__(256) void split_kernel(
    const float* __restrict__ src, __nv_bfloat16* __restrict__ hi,
    __nv_bfloat16* __restrict__ lo)
{
    size_t i = (size_t)(blockIdx.x * 256 + threadIdx.x) * 4;
    float4 v = *(const float4*)(src + i);
    __nv_bfloat16 h0 = __float2bfloat16_rn(v.x);
    __nv_bfloat16 h1 = __float2bfloat16_rn(v.y);
    __nv_bfloat16 h2 = __float2bfloat16_rn(v.z);
    __nv_bfloat16 h3 = __float2bfloat16_rn(v.w);
    __nv_bfloat16 l0 = __float2bfloat16_rn(v.x - __bfloat162float(h0));
    __nv_bfloat16 l1 = __float2bfloat16_rn(v.y - __bfloat162float(h1));
    __nv_bfloat16 l2 = __float2bfloat16_rn(v.z - __bfloat162float(h2));
    __nv_bfloat16 l3 = __float2bfloat16_rn(v.w - __bfloat162float(h3));
    ((__nv_bfloat162*)(hi + i))[0] = __nv_bfloat162(h0, h1);
    ((__nv_bfloat162*)(hi + i))[1] = __nv_bfloat162(h2, h3);
    ((__nv_bfloat162*)(lo + i))[0] = __nv_bfloat162(l0, l1);
    ((__nv_bfloat162*)(lo + i))[1] = __nv_bfloat162(l2, l3);
}

// ---------------------------------------------------------------------------
// Prep: transpose + split the 4 weight matrices W[k][n] -> Wt_hi/lo[n][k]
// ---------------------------------------------------------------------------
__global__ __launch_bounds__(256) void wsplit_kernel(
    const float* __restrict__ W0, const float* __restrict__ W1,
    const float* __restrict__ W2, const float* __restrict__ W3)
{
    __shared__ float t[32][33];
    const float* W = (blockIdx.z == 0) ? W0 : (blockIdx.z == 1) ? W1
                   : (blockIdx.z == 2) ? W2 : W3;
    __nv_bfloat16* whi = g_bf + BF_WT + (size_t)(2 * blockIdx.z) * DM * DM;
    __nv_bfloat16* wlo = whi + (size_t)DM * DM;
    int tx = threadIdx.x, ty = threadIdx.y;
    int n = blockIdx.x * 32 + tx;
#pragma unroll
    for (int i = 0; i < 32; i += 8)
        t[ty + i][tx] = W[(size_t)(blockIdx.y * 32 + ty + i) * DM + n];
    __syncthreads();
#pragma unroll
    for (int i = 0; i < 32; i += 8) {
        float v = t[tx][ty + i];
        __nv_bfloat16 h = __float2bfloat16_rn(v);
        __nv_bfloat16 l = __float2bfloat16_rn(v - __bfloat162float(h));
        size_t o = (size_t)(blockIdx.x * 32 + ty + i) * DM + blockIdx.y * 32 + tx;
        whi[o] = h;
        wlo[o] = l;
    }
}

// ---------------------------------------------------------------------------
// RoPE cos/sin table: (s, j) -> g_rope[2*(s*32+j)] = {cos, sin}
// ---------------------------------------------------------------------------
__global__ __launch_bounds__(256) void rope_table_kernel()
{
    int i = blockIdx.x * 256 + threadIdx.x;   // 0 .. 65535
    int s = i >> 5, j = i & 31;
    float invf = (float)pow(10000.0, -(double)j / 32.0);
    float ang = (float)s * invf;
    float sn, c;
    sincosf(ang, &sn, &c);
    g_rope[2 * i]     = c;
    g_rope[2 * i + 1] = sn;
}

// ---------------------------------------------------------------------------
// mma.sync bf16-split GEMM, 3-stage cp.async pipeline, fused epilogues.
// B fragments loaded pairwise with ldm_x4 (2 n8-tiles per instruction).
// MODE 0: C = acc + bias (fp32, row-major)
// MODE 1: Vt hi/lo bf16, transposed write [(bh*64+d)][s]  (vectorized x4)
// MODE 2: RoPE (table) + opt 0.125 scale + bf16 hi/lo split (vectorized x4)
// ---------------------------------------------------------------------------
#define KCH 32
#define NKT (DM / KCH)             // 32 chunks
#define STG_T 8192
#define STG_B (4 * STG_T)          // 32 KB per stage
#define MM_SMEM (3 * STG_B + 1024)

template <int MODE>
__global__ __launch_bounds__(256, 2) void mm_gemm(
    const __nv_bfloat16* __restrict__ Ahi, const __nv_bfloat16* __restrict__ Alo,
    const __nv_bfloat16* __restrict__ Bhi, const __nv_bfloat16* __restrict__ Blo,
    const float* __restrict__ bias, float* __restrict__ C,
    __nv_bfloat16* __restrict__ Dhi, __nv_bfloat16* __restrict__ Dlo,
    int scaleQ)
{
    extern __shared__ char smraw[];
    const uint32_t sbase = (smem_u32(smraw) + 1023) & ~1023u;

    const int tid  = threadIdx.x;
    const int wid  = tid >> 5, lane = tid & 31;
    const int m0   = blockIdx.y * 128, n0 = blockIdx.x * 128;
    const int wm   = (wid >> 2) * 64, wn = (wid & 3) * 32;

    float acc[4][4][4];
#pragma unroll
    for (int i = 0; i < 4; i++)
#pragma unroll
        for (int j = 0; j < 4; j++)
#pragma unroll
            for (int r = 0; r < 4; r++) acc[i][j][r] = 0.f;

    auto load_stage = [&](int kt, int slot) {
        const uint32_t bb = sbase + slot * STG_B;
#pragma unroll
        for (int it = 0; it < 8; it++) {
            int i = it * 256 + tid;
            int tile = i >> 9, idx = i & 511;
            int r = idx >> 2, c = idx & 3;
            uint32_t dst = bb + tile * STG_T + sw64((uint32_t)(r * 64 + c * 16));
            size_t off = (tile < 2)
                ? (size_t)(m0 + r) * DM + kt * KCH + c * 8
                : (size_t)(n0 + r) * DM + kt * KCH + c * 8;
            const __nv_bfloat16* src =
                (tile == 0) ? Ahi + off : (tile == 1) ? Alo + off
              : (tile == 2) ? Bhi + off : Blo + off;
            cp_async16(dst, src);
        }
    };

    load_stage(0, 0); CP_COMMIT();
    load_stage(1, 1); CP_COMMIT();

    int slot = 0;
    for (int kt = 0; kt < NKT; kt++) {
        CP_WAIT(1);
        __syncthreads();
        if (kt + 2 < NKT) {
            int ns = slot + 2; if (ns >= 3) ns -= 3;
            load_stage(kt + 2, ns);
            CP_COMMIT();
        } else {
            CP_COMMIT();
        }

        const uint32_t bb = sbase + slot * STG_B;
#pragma unroll
        for (int ks = 0; ks < 2; ks++) {
            uint32_t ah[4][4], al[4][4];
#pragma unroll
            for (int mt = 0; mt < 4; mt++) {
                int row = wm + mt * 16 + (lane & 15);
                int c = ks * 2 + (lane >> 4);
                uint32_t so = sw64((uint32_t)(row * 64 + c * 16));
                ldm_x4(ah[mt], bb + 0 * STG_T + so);
                ldm_x4(al[mt], bb + 1 * STG_T + so);
            }
            // B frags: one ldm_x4 covers two adjacent n8 tiles
            uint32_t bh[4][2], bl[4][2];
#pragma unroll
            for (int np = 0; np < 2; np++) {
                int row = wn + np * 16 + (lane & 7) + ((lane >> 4) << 3);
                int c = ks * 2 + ((lane >> 3) & 1);
                uint32_t so = sw64((uint32_t)(row * 64 + c * 16));
                uint32_t r4[4];
                ldm_x4(r4, bb + 2 * STG_T + so);
                bh[np * 2][0] = r4[0]; bh[np * 2][1] = r4[1];
                bh[np * 2 + 1][0] = r4[2]; bh[np * 2 + 1][1] = r4[3];
                ldm_x4(r4, bb + 3 * STG_T + so);
                bl[np * 2][0] = r4[0]; bl[np * 2][1] = r4[1];
                bl[np * 2 + 1][0] = r4[2]; bl[np * 2 + 1][1] = r4[3];
            }
#pragma unroll
            for (int mt = 0; mt < 4; mt++)
#pragma unroll
                for (int nt = 0; nt < 4; nt++) {
                    mma_bf16(acc[mt][nt], ah[mt], bh[nt]);
                    mma_bf16(acc[mt][nt], ah[mt], bl[nt]);
                    mma_bf16(acc[mt][nt], al[mt], bh[nt]);
                }
        }
        if (++slot == 3) slot = 0;
    }

    const int g = lane >> 2, t = lane & 3;

    if (MODE == 0) {
        // ---- plain fp32 + bias ----
#pragma unroll
        for (int mt = 0; mt < 4; mt++) {
            int r0 = m0 + wm + mt * 16 + g;
#pragma unroll
            for (int nt = 0; nt < 4; nt++) {
                int col = n0 + wn + nt * 8 + t * 2;
                float2 bv = *(const float2*)&bias[col];
                float2 o0, o1;
                o0.x = acc[mt][nt][0] + bv.x;
                o0.y = acc[mt][nt][1] + bv.y;
                o1.x = acc[mt][nt][2] + bv.x;
                o1.y = acc[mt][nt][3] + bv.y;
                *(float2*)&C[(size_t)r0 * DM + col] = o0;
                *(float2*)&C[(size_t)(r0 + 8) * DM + col] = o1;
            }
        }
        return;
    }

    // ---- staged epilogues: tile -> smem fp32 [128][129] (reuse stages) ----
    __syncthreads();                       // all ldmatrix reads done
    float* csm = (float*)smraw;
#pragma unroll
    for (int mt = 0; mt < 4; mt++) {
        int r0 = wm + mt * 16 + g;
#pragma unroll
        for (int nt = 0; nt < 4; nt++) {
            int col = wn + nt * 8 + t * 2;
            float2 bv = *(const float2*)&bias[n0 + col];
            csm[r0 * 129 + col]           = acc[mt][nt][0] + bv.x;
            csm[r0 * 129 + col + 1]       = acc[mt][nt][1] + bv.y;
            csm[(r0 + 8) * 129 + col]     = acc[mt][nt][2] + bv.x;
            csm[(r0 + 8) * 129 + col + 1] = acc[mt][nt][3] + bv.y;
        }
    }
    __syncthreads();

    if (MODE == 1) {
        // ---- Vt: [(bh*64+d)][s] bf16 hi/lo, 4 consecutive s per thread ----
#pragma unroll
        for (int i = 0; i < 16; i++) {
            int idx = i * 256 + tid;           // 0..4095 (chunks of 4 s)
            int drow = idx >> 5, s4 = (idx & 31) * 4;
            float v0 = csm[(s4 + 0) * 129 + drow];
            float v1 = csm[(s4 + 1) * 129 + drow];
            float v2 = csm[(s4 + 2) * 129 + drow];
            float v3 = csm[(s4 + 3) * 129 + drow];
            int m = m0 + s4, b = m >> 11, s = m & (SQ - 1);
            int ncol = n0 + drow, h = ncol >> 6, d = ncol & 63;
            size_t o = (size_t)((b * NH + h) * DKH + d) * SQ + s;
            float h0 = __bfloat162float(__float2bfloat16_rn(v0));
            float h1 = __bfloat162float(__float2bfloat16_rn(v1));
            float h2 = __bfloat162float(__float2bfloat16_rn(v2));
            float h3 = __bfloat162float(__float2bfloat16_rn(v3));
            uint2 hv, lv;
            hv.x = packbf2(h0, h1); hv.y = packbf2(h2, h3);
            lv.x = packbf2(v0 - h0, v1 - h1);
            lv.y = packbf2(v2 - h2, v3 - h3);
            *(uint2*)&Dhi[o] = hv;
            *(uint2*)&Dlo[o] = lv;
        }
    } else {
        // ---- MODE 2: RoPE + (opt) scale + hi/lo split, 4 n per thread ----
        float sc = scaleQ ? 0.125f : 1.0f;
#pragma unroll
        for (int i = 0; i < 16; i++) {
            int idx = i * 256 + tid;           // 0..4095 (chunks of 4 n)
            int row = idx >> 5, n4 = (idx & 31) * 4;
            int d = n4 & 63, j = d & 31, hb = n4 & 64;
            int m = m0 + row, s = m & (SQ - 1);
            const float* cr = csm + row * 129 + hb;
            float r[4];
            bool first = (d < 32);
#pragma unroll
            for (int e = 0; e < 4; e++) {
                int jj = j + e;
                float x1 = cr[jj], x2 = cr[jj + 32];
                float2 cs = *(const float2*)&g_rope[2 * (s * 32 + jj)];
                r[e] = first ? (x1 * cs.x - x2 * cs.y)
                             : (x1 * cs.y + x2 * cs.x);
                r[e] *= sc;
            }
            float h0 = __bfloat162float(__float2bfloat16_rn(r[0]));
            float h1 = __bfloat162float(__float2bfloat16_rn(r[1]));
            float h2 = __bfloat162float(__float2bfloat16_rn(r[2]));
            float h3 = __bfloat162float(__float2bfloat16_rn(r[3]));
            uint2 hv, lv;
            hv.x = packbf2(h0, h1); hv.y = packbf2(h2, h3);
            lv.x = packbf2(r[0] - h0, r[1] - h1);
            lv.y = packbf2(r[2] - h2, r[3] - h3);
            size_t o = (size_t)m * DM + n0 + n4;
            *(uint2*)&Dhi[o] = hv;
            *(uint2*)&Dlo[o] = lv;
        }
    }
}

// ---------------------------------------------------------------------------
// Tensor-core flash attention; K/V fragments via pairwise ldm_x4.
// ---------------------------------------------------------------------------
#define FS_QH 0
#define FS_QL 16384
#define FS_ST 32768
#define FS_STB 32768
#define FA3_SMEM (FS_ST + 2 * FS_STB + 1024)

__global__ __launch_bounds__(256, 2) void flash_tc()
{
    extern __shared__ char smraw[];
    const uint32_t sb = (smem_u32(smraw) + 1023) & ~1023u;

    const int tid = threadIdx.x;
    const int wid = tid >> 5, lane = tid & 31;
    const int bh = blockIdx.y, b = bh >> 4, h = bh & 15;
    const int q0 = blockIdx.x * 128;

    const __nv_bfloat16* Qh = g_bf + BF_QHI + (size_t)(b * SQ + q0) * DM + h * DKH;
    const __nv_bfloat16* Ql = g_bf + BF_QLO + (size_t)(b * SQ + q0) * DM + h * DKH;
    const __nv_bfloat16* Kh = g_bf + BF_KHI + (size_t)(b * SQ) * DM + h * DKH;
    const __nv_bfloat16* Kl = g_bf + BF_KLO + (size_t)(b * SQ) * DM + h * DKH;
    const __nv_bfloat16* Vh = g_bf + BF_VTHI + (size_t)(bh * DKH) * SQ;
    const __nv_bfloat16* Vl = g_bf + BF_VTLO + (size_t)(bh * DKH) * SQ;

#pragma unroll
    for (int it = 0; it < 8; it++) {
        int i = it * 256 + tid;            // 0..2047
        int arr = i >> 10, idx = i & 1023;
        int row = idx >> 3, c8 = idx & 7;
        const __nv_bfloat16* src = (arr ? Ql : Qh) + (size_t)row * DM + c8 * 8;
        uint32_t dst = sb + (arr ? FS_QL : FS_QH)
                     + sw128((uint32_t)(row * 128 + c8 * 16));
        cp_async16(dst, src);
    }
    CP_COMMIT();

    auto load_stage = [&](int ktile, int buf) {
        const uint32_t bb = sb + FS_ST + buf * FS_STB;
#pragma unroll
        for (int it = 0; it < 8; it++) {
            int i = it * 256 + tid;        // 0..2047
            int tile = i >> 9, idx = i & 511;
            int row = idx >> 3, c8 = idx & 7;
            const __nv_bfloat16* src;
            if (tile < 2) {
                src = (tile ? Kl : Kh)
                    + (size_t)(ktile * 64 + row) * DM + c8 * 8;
            } else {
                src = ((tile == 3) ? Vl : Vh)
                    + (size_t)row * SQ + ktile * 64 + c8 * 8;
            }
            uint32_t dst = bb + (tile << 13)
                         + sw128((uint32_t)(row * 128 + c8 * 16));
            cp_async16(dst, src);
        }
    };

    load_stage(0, 0);
    CP_COMMIT();
    CP_WAIT(1);                // Q arrived
    __syncthreads();

    uint32_t qh[4][4], ql[4][4];
#pragma unroll
    for (int kt = 0; kt < 4; kt++) {
        int row = wid * 16 + (lane & 15);
        uint32_t so = sw128((uint32_t)(row * 128 + kt * 32 + (lane >> 4) * 16));
        ldm_x4(qh[kt], sb + FS_QH + so);
        ldm_x4(ql[kt], sb + FS_QL + so);
    }

    float m_i[2] = {-1e30f, -1e30f};
    float l_i[2] = {0.f, 0.f};
    float o[8][4];
#pragma unroll
    for (int nt = 0; nt < 8; nt++)
#pragma unroll
        for (int r = 0; r < 4; r++) o[nt][r] = 0.f;

    for (int ktile = 0; ktile < SQ / 64; ktile++) {
        const int buf = ktile & 1;
        if (ktile < SQ / 64 - 1) {
            load_stage(ktile + 1, buf ^ 1);
            CP_COMMIT();
            CP_WAIT(1);
        } else {
            CP_WAIT(0);
        }
        __syncthreads();

        const uint32_t bb = sb + FS_ST + buf * FS_STB;
        const uint32_t KH = bb, KL = bb + 8192, VH = bb + 16384, VL = bb + 24576;

        float sacc[8][4];
#pragma unroll
        for (int nt = 0; nt < 8; nt++)
#pragma unroll
            for (int r = 0; r < 4; r++) sacc[nt][r] = 0.f;

#pragma unroll
        for (int kt = 0; kt < 4; kt++) {
            uint32_t bhf[8][2], blf[8][2];
#pragma unroll
            for (int np = 0; np < 4; np++) {
                int row = np * 16 + (lane & 7) + ((lane >> 4) << 3);
                uint32_t so = sw128((uint32_t)(row * 128 + kt * 32
                                               + ((lane >> 3) & 1) * 16));
                uint32_t r4[4];
                ldm_x4(r4, KH + so);
                bhf[np * 2][0] = r4[0]; bhf[np * 2][1] = r4[1];
                bhf[np * 2 + 1][0] = r4[2]; bhf[np * 2 + 1][1] = r4[3];
                ldm_x4(r4, KL + so);
                blf[np * 2][0] = r4[0]; blf[np * 2][1] = r4[1];
                blf[np * 2 + 1][0] = r4[2]; blf[np * 2 + 1][1] = r4[3];
            }
#pragma unroll
            for (int nt = 0; nt < 8; nt++) {
                mma_bf16(sacc[nt], qh[kt], bhf[nt]);
                mma_bf16(sacc[nt], qh[kt], blf[nt]);
                mma_bf16(sacc[nt], ql[kt], bhf[nt]);
            }
        }

        float mx0 = -1e30f, mx1 = -1e30f;
#pragma unroll
        for (int nt = 0; nt < 8; nt++) {
            mx0 = fmaxf(mx0, fmaxf(sacc[nt][0], sacc[nt][1]));
            mx1 = fmaxf(mx1, fmaxf(sacc[nt][2], sacc[nt][3]));
        }
        mx0 = fmaxf(mx0, __shfl_xor_sync(0xffffffffu, mx0, 1));
        mx0 = fmaxf(mx0, __shfl_xor_sync(0xffffffffu, mx0, 2));
        mx1 = fmaxf(mx1, __shfl_xor_sync(0xffffffffu, mx1, 1));
        mx1 = fmaxf(mx1, __shfl_xor_sync(0xffffffffu, mx1, 2));
        float mn0 = fmaxf(m_i[0], mx0), mn1 = fmaxf(m_i[1], mx1);
        float al0 = __expf(m_i[0] - mn0), al1 = __expf(m_i[1] - mn1);
        float rs0 = 0.f, rs1 = 0.f;
#pragma unroll
        for (int nt = 0; nt < 8; nt++) {
            sacc[nt][0] = __expf(sacc[nt][0] - mn0);
            sacc[nt][1] = __expf(sacc[nt][1] - mn0);
            sacc[nt][2] = __expf(sacc[nt][2] - mn1);
            sacc[nt][3] = __expf(sacc[nt][3] - mn1);
            rs0 += sacc[nt][0] + sacc[nt][1];
            rs1 += sacc[nt][2] + sacc[nt][3];
        }
        rs0 += __shfl_xor_sync(0xffffffffu, rs0, 1);
        rs0 += __shfl_xor_sync(0xffffffffu, rs0, 2);
        rs1 += __shfl_xor_sync(0xffffffffu, rs1, 1);
        rs1 += __shfl_xor_sync(0xffffffffu, rs1, 2);
        l_i[0] = l_i[0] * al0 + rs0;
        l_i[1] = l_i[1] * al1 + rs1;
        m_i[0] = mn0; m_i[1] = mn1;
#pragma unroll
        for (int nt = 0; nt < 8; nt++) {
            o[nt][0] *= al0; o[nt][1] *= al0;
            o[nt][2] *= al1; o[nt][3] *= al1;
        }

#pragma unroll
        for (int t = 0; t < 4; t++) {
            float p00 = sacc[2 * t][0], p01 = sacc[2 * t][1];
            float p02 = sacc[2 * t][2], p03 = sacc[2 * t][3];
            float p10 = sacc[2 * t + 1][0], p11 = sacc[2 * t + 1][1];
            float p12 = sacc[2 * t + 1][2], p13 = sacc[2 * t + 1][3];
            float h00 = __bfloat162float(__float2bfloat16_rn(p00));
            float h01 = __bfloat162float(__float2bfloat16_rn(p01));
            float h02 = __bfloat162float(__float2bfloat16_rn(p02));
            float h03 = __bfloat162float(__float2bfloat16_rn(p03));
            float h10 = __bfloat162float(__float2bfloat16_rn(p10));
            float h11 = __bfloat162float(__float2bfloat16_rn(p11));
            float h12 = __bfloat162float(__float2bfloat16_rn(p12));
            float h13 = __bfloat162float(__float2bfloat16_rn(p13));
            uint32_t ahf[4], alf[4];
            ahf[0] = packbf2(h00, h01); ahf[1] = packbf2(h02, h03);
            ahf[2] = packbf2(h10, h11); ahf[3] = packbf2(h12, h13);
            alf[0] = packbf2(p00 - h00, p01 - h01);
            alf[1] = packbf2(p02 - h02, p03 - h03);
            alf[2] = packbf2(p10 - h10, p11 - h11);
            alf[3] = packbf2(p12 - h12, p13 - h13);
#pragma unroll
            for (int np = 0; np < 4; np++) {
                uint32_t r4[4], vh0[2], vh1[2], vl0[2], vl1[2];
                int row = np * 16 + (lane & 7) + ((lane >> 4) << 3);
                uint32_t so = sw128((uint32_t)(row * 128 + t * 32
                                               + ((lane >> 3) & 1) * 16));
                ldm_x4(r4, VH + so);
                vh0[0] = r4[0]; vh0[1] = r4[1]; vh1[0] = r4[2]; vh1[1] = r4[3];
                ldm_x4(r4, VL + so);
                vl0[0] = r4[0]; vl0[1] = r4[1]; vl1[0] = r4[2]; vl1[1] = r4[3];
                mma_bf16(o[np * 2], ahf, vh0);
                mma_bf16(o[np * 2], ahf, vl0);
                mma_bf16(o[np * 2], alf, vh0);
                mma_bf16(o[np * 2 + 1], ahf, vh1);
                mma_bf16(o[np * 2 + 1], ahf, vl1);
                mma_bf16(o[np * 2 + 1], alf, vh1);
            }
        }
        __syncthreads();
    }

    // ---- epilogue: divide by l, bf16 hi/lo split, store a_hi/a_lo ----
    float inv0 = 1.f / l_i[0], inv1 = 1.f / l_i[1];
    int r0 = q0 + wid * 16 + (lane >> 2);
    __nv_bfloat16* Ah = g_bf + BF_AHI + (size_t)(b * SQ) * DM + h * DKH;
    __nv_bfloat16* Al = g_bf + BF_ALO + (size_t)(b * SQ) * DM + h * DKH;
#pragma unroll
    for (int nt = 0; nt < 8; nt++) {
        int col = nt * 8 + (lane & 3) * 2;
        float a0 = o[nt][0] * inv0, a1 = o[nt][1] * inv0;
        float a2 = o[nt][2] * inv1, a3 = o[nt][3] * inv1;
        float h0 = __bfloat162float(__float2bfloat16_rn(a0));
        float h1 = __bfloat162float(__float2bfloat16_rn(a1));
        float h2 = __bfloat162float(__float2bfloat16_rn(a2));
        float h3 = __bfloat162float(__float2bfloat16_rn(a3));
        *(uint32_t*)&Ah[(size_t)r0 * DM + col]       = packbf2(h0, h1);
        *(uint32_t*)&Al[(size_t)r0 * DM + col]       = packbf2(a0 - h0, a1 - h1);
        *(uint32_t*)&Ah[(size_t)(r0 + 8) * DM + col] = packbf2(h2, h3);
        *(uint32_t*)&Al[(size_t)(r0 + 8) * DM + col] = packbf2(a2 - h2, a3 - h3);
    }
}

// ---------------------------------------------------------------------------
extern "C" void kernel_launch(void* const* d_in, const int* in_sizes, int n_in,
                              void* d_out, int out_size)
{
    const float* x  = (const float*)d_in[0];
    const float* Wq = (const float*)d_in[1];
    const float* bq = (const float*)d_in[2];
    const float* Wk = (const float*)d_in[3];
    const float* bk = (const float*)d_in[4];
    const float* Wv = (const float*)d_in[5];
    const float* bv = (const float*)d_in[6];
    const float* Wo = (const float*)d_in[7];
    const float* bo = (const float*)d_in[8];
    float* out = (float*)d_out;

    __nv_bfloat16* bf = nullptr;
    cudaGetSymbolAddress((void**)&bf, g_bf);

    cudaFuncSetAttribute(mm_gemm<0>,
                         cudaFuncAttributeMaxDynamicSharedMemorySize, MM_SMEM);
    cudaFuncSetAttribute(mm_gemm<1>,
                         cudaFuncAttributeMaxDynamicSharedMemorySize, MM_SMEM);
    cudaFuncSetAttribute(mm_gemm<2>,
                         cudaFuncAttributeMaxDynamicSharedMemorySize, MM_SMEM);
    cudaFuncSetAttribute(flash_tc,
                         cudaFuncAttributeMaxDynamicSharedMemorySize, FA3_SMEM);

    // 1) prep: rope table, x split, weight transpose+split
    rope_table_kernel<<<SQ * 32 / 256, 256>>>();
    split_kernel<<<MROWS * DM / 1024, 256>>>(x, bf + BF_XHI, bf + BF_XLO);
    wsplit_kernel<<<dim3(32, 32, 4), dim3(32, 8)>>>(Wq, Wk, Wv, Wo);

    // 2) Q/K/V projections with fused (vectorized) epilogues
    mm_gemm<2><<<dim3(8, 32), 256, MM_SMEM>>>(
        bf + BF_XHI, bf + BF_XLO,
        bf + BF_WT + 0ull * DM * DM, bf + BF_WT + 1ull * DM * DM, bq,
        nullptr, bf + BF_QHI, bf + BF_QLO, 1);
    mm_gemm<2><<<dim3(8, 32), 256, MM_SMEM>>>(
        bf + BF_XHI, bf + BF_XLO,
        bf + BF_WT + 2ull * DM * DM, bf + BF_WT + 3ull * DM * DM, bk,
        nullptr, bf + BF_KHI, bf + BF_KLO, 0);
    mm_gemm<1><<<dim3(8, 32), 256, MM_SMEM>>>(
        bf + BF_XHI, bf + BF_XLO,
        bf + BF_WT + 4ull * DM * DM, bf + BF_WT + 5ull * DM * DM, bv,
        nullptr, bf + BF_VTHI, bf + BF_VTLO, 0);

    // 3) Flash attention (writes a_hi/a_lo bf16 directly)
    flash_tc<<<dim3(SQ / 128, NB * NH), 256, FA3_SMEM>>>();

    // 4) output projection (fp32 out)
    mm_gemm<0><<<dim3(8, 32), 256, MM_SMEM>>>(
        bf + BF_AHI, bf + BF_ALO,
        bf + BF_WT + 6ull * DM * DM, bf + BF_WT + 7ull * DM * DM, bo,
        out, nullptr, nullptr, 0);
}

// round 15
// speedup vs baseline: 1.1981x; 1.1005x over previous
#include <cuda_runtime.h>
#include <cuda_bf16.h>
#include <cuda_fp16.h>
#include <math.h>
#include <stdint.h>

#define SQ   2048
#define NB   2
#define NH   16
#define DKH  64
#define DM   1024
#define MROWS 4096   // NB*SQ

// ---------------------------------------------------------------------------
// Scratch (__device__ globals; allocation-free rule)
// ---------------------------------------------------------------------------
__device__ float g_rope[SQ * 32 * 2];                    // cos,sin per (s,j)

// 2-byte scratch offsets (elements; MROWS*DM = 4M, DM*DM = 1M)
#define BF_XHI  0ull
#define BF_XLO  (1ull * MROWS * DM)
#define BF_WT   (2ull * MROWS * DM)                       // 8 x DM*DM
#define BF_AHI  (BF_WT + 8ull * DM * DM)
#define BF_ALO  (BF_AHI + 1ull * MROWS * DM)
#define BF_QHI  (BF_ALO + 1ull * MROWS * DM)
#define BF_QLO  (BF_QHI + 1ull * MROWS * DM)
#define BF_KHI  (BF_QLO + 1ull * MROWS * DM)
#define BF_KLO  (BF_KHI + 1ull * MROWS * DM)
#define BF_VTHI (BF_KLO + 1ull * MROWS * DM)              // fp16 payload
#define BF_VTLO (BF_VTHI + 1ull * MROWS * DM)             // fp16 payload
__device__ __nv_bfloat16 g_bf[BF_VTLO + 1ull * MROWS * DM];

// ---------------------------------------------------------------------------
// Helpers (sm_100-safe: cp.async, ldmatrix, mma.sync only)
// ---------------------------------------------------------------------------
__device__ __forceinline__ uint32_t smem_u32(const void* p) {
    uint32_t a;
    asm("{ .reg .u64 t; cvta.to.shared.u64 t, %1; cvt.u32.u64 %0, t; }"
        : "=r"(a) : "l"(p));
    return a;
}

__device__ __forceinline__ uint32_t sw64(uint32_t off) {
    return off ^ ((off >> 3) & 0x30);
}
__device__ __forceinline__ uint32_t sw128(uint32_t off) {
    return off ^ ((off >> 3) & 0x70);
}

__device__ __forceinline__ void ldm_x4(uint32_t* r, uint32_t addr) {
    asm volatile("ldmatrix.sync.aligned.m8n8.x4.shared.b16 {%0,%1,%2,%3}, [%4];"
                 : "=r"(r[0]), "=r"(r[1]), "=r"(r[2]), "=r"(r[3]) : "r"(addr));
}

__device__ __forceinline__ void mma_bf16(float* d, const uint32_t* a,
                                         const uint32_t* b) {
    asm volatile(
        "mma.sync.aligned.m16n8k16.row.col.f32.bf16.bf16.f32 "
        "{%0,%1,%2,%3}, {%4,%5,%6,%7}, {%8,%9}, {%0,%1,%2,%3};"
        : "+f"(d[0]), "+f"(d[1]), "+f"(d[2]), "+f"(d[3])
        : "r"(a[0]), "r"(a[1]), "r"(a[2]), "r"(a[3]), "r"(b[0]), "r"(b[1]));
}

__device__ __forceinline__ void mma_f16(float* d, const uint32_t* a,
                                        const uint32_t* b) {
    asm volatile(
        "mma.sync.aligned.m16n8k16.row.col.f32.f16.f16.f32 "
        "{%0,%1,%2,%3}, {%4,%5,%6,%7}, {%8,%9}, {%0,%1,%2,%3};"
        : "+f"(d[0]), "+f"(d[1]), "+f"(d[2]), "+f"(d[3])
        : "r"(a[0]), "r"(a[1]), "r"(a[2]), "r"(a[3]), "r"(b[0]), "r"(b[1]));
}

__device__ __forceinline__ void cp_async16(uint32_t dst, const void* src) {
    asm volatile("cp.async.cg.shared.global [%0], [%1], 16;"
                 :: "r"(dst), "l"(src));
}
#define CP_COMMIT() asm volatile("cp.async.commit_group;" ::: "memory")
#define CP_WAIT(n)  asm volatile("cp.async.wait_group %0;" :: "n"(n) : "memory")

__device__ __forceinline__ uint32_t packbf2(float a, float b) {
    __nv_bfloat162 t = __floats2bfloat162_rn(a, b);
    return *(uint32_t*)&t;
}
__device__ __forceinline__ uint32_t packh2(float a, float b) {
    __half2 t = __floats2half2_rn(a, b);
    return *(uint32_t*)&t;
}

// ---------------------------------------------------------------------------
// Prep: fp32 -> (bf16 hi, bf16 lo) split, 4 elems/thread
// ---------------------------------------------------------------------------
__global__ __launch_bounds__(256) void split_kernel(
    const float* __restrict__ src, __nv_bfloat16* __restrict__ hi,
    __nv_bfloat16* __restrict__ lo)
{
    size_t i = (size_t)(blockIdx.x * 256 + threadIdx.x) * 4;
    float4 v = *(const float4*)(src + i);
    __nv_bfloat16 h0 = __float2bfloat16_rn(v.x);
    __nv_bfloat16 h1 = __float2bfloat16_rn(v.y);
    __nv_bfloat16 h2 = __float2bfloat16_rn(v.z);
    __nv_bfloat16 h3 = __float2bfloat16_rn(v.w);
    __nv_bfloat16 l0 = __float2bfloat16_rn(v.x - __bfloat162float(h0));
    __nv_bfloat16 l1 = __float2bfloat16_rn(v.y - __bfloat162float(h1));
    __nv_bfloat16 l2 = __float2bfloat16_rn(v.z - __bfloat162float(h2));
    __nv_bfloat16 l3 = __float2bfloat16_rn(v.w - __bfloat162float(h3));
    ((__nv_bfloat162*)(hi + i))[0] = __nv_bfloat162(h0, h1);
    ((__nv_bfloat162*)(hi + i))[1] = __nv_bfloat162(h2, h3);
    ((__nv_bfloat162*)(lo + i))[0] = __nv_bfloat162(l0, l1);
    ((__nv_bfloat162*)(lo + i))[1] = __nv_bfloat162(l2, l3);
}

// ---------------------------------------------------------------------------
// Prep: transpose + split the 4 weight matrices W[k][n] -> Wt_hi/lo[n][k]
// ---------------------------------------------------------------------------
__global__ __launch_bounds__(256) void wsplit_kernel(
    const float* __restrict__ W0, const float* __restrict__ W1,
    const float* __restrict__ W2, const float* __restrict__ W3)
{
    __shared__ float t[32][33];
    const float* W = (blockIdx.z == 0) ? W0 : (blockIdx.z == 1) ? W1
                   : (blockIdx.z == 2) ? W2 : W3;
    __nv_bfloat16* whi = g_bf + BF_WT + (size_t)(2 * blockIdx.z) * DM * DM;
    __nv_bfloat16* wlo = whi + (size_t)DM * DM;
    int tx = threadIdx.x, ty = threadIdx.y;
    int n = blockIdx.x * 32 + tx;
#pragma unroll
    for (int i = 0; i < 32; i += 8)
        t[ty + i][tx] = W[(size_t)(blockIdx.y * 32 + ty + i) * DM + n];
    __syncthreads();
#pragma unroll
    for (int i = 0; i < 32; i += 8) {
        float v = t[tx][ty + i];
        __nv_bfloat16 h = __float2bfloat16_rn(v);
        __nv_bfloat16 l = __float2bfloat16_rn(v - __bfloat162float(h));
        size_t o = (size_t)(blockIdx.x * 32 + ty + i) * DM + blockIdx.y * 32 + tx;
        whi[o] = h;
        wlo[o] = l;
    }
}

// ---------------------------------------------------------------------------
// RoPE cos/sin table: (s, j) -> g_rope[2*(s*32+j)] = {cos, sin}
// ---------------------------------------------------------------------------
__global__ __launch_bounds__(256) void rope_table_kernel()
{
    int i = blockIdx.x * 256 + threadIdx.x;   // 0 .. 65535
    int s = i >> 5, j = i & 31;
    float invf = (float)pow(10000.0, -(double)j / 32.0);
    float ang = (float)s * invf;
    float sn, c;
    sincosf(ang, &sn, &c);
    g_rope[2 * i]     = c;
    g_rope[2 * i + 1] = sn;
}

// ---------------------------------------------------------------------------
// mma.sync bf16-split GEMM, 3-stage cp.async pipeline, fused epilogues.
// B fragments loaded pairwise with ldm_x4 (2 n8-tiles per instruction).
// MODE 0: C = acc + bias (fp32, row-major)
// MODE 1: Vt hi/lo FP16, transposed write [(bh*64+d)][s]  (vectorized x4)
// MODE 2: RoPE (table) + opt 0.125 scale + bf16 hi/lo split (vectorized x4)
// ---------------------------------------------------------------------------
#define KCH 32
#define NKT (DM / KCH)             // 32 chunks
#define STG_T 8192
#define STG_B (4 * STG_T)          // 32 KB per stage
#define MM_SMEM (3 * STG_B + 1024)

template <int MODE>
__global__ __launch_bounds__(256, 2) void mm_gemm(
    const __nv_bfloat16* __restrict__ Ahi, const __nv_bfloat16* __restrict__ Alo,
    const __nv_bfloat16* __restrict__ Bhi, const __nv_bfloat16* __restrict__ Blo,
    const float* __restrict__ bias, float* __restrict__ C,
    __nv_bfloat16* __restrict__ Dhi, __nv_bfloat16* __restrict__ Dlo,
    int scaleQ)
{
    extern __shared__ char smraw[];
    const uint32_t sbase = (smem_u32(smraw) + 1023) & ~1023u;

    const int tid  = threadIdx.x;
    const int wid  = tid >> 5, lane = tid & 31;
    const int m0   = blockIdx.y * 128, n0 = blockIdx.x * 128;
    const int wm   = (wid >> 2) * 64, wn = (wid & 3) * 32;

    float acc[4][4][4];
#pragma unroll
    for (int i = 0; i < 4; i++)
#pragma unroll
        for (int j = 0; j < 4; j++)
#pragma unroll
            for (int r = 0; r < 4; r++) acc[i][j][r] = 0.f;

    auto load_stage = [&](int kt, int slot) {
        const uint32_t bb = sbase + slot * STG_B;
#pragma unroll
        for (int it = 0; it < 8; it++) {
            int i = it * 256 + tid;
            int tile = i >> 9, idx = i & 511;
            int r = idx >> 2, c = idx & 3;
            uint32_t dst = bb + tile * STG_T + sw64((uint32_t)(r * 64 + c * 16));
            size_t off = (tile < 2)
                ? (size_t)(m0 + r) * DM + kt * KCH + c * 8
                : (size_t)(n0 + r) * DM + kt * KCH + c * 8;
            const __nv_bfloat16* src =
                (tile == 0) ? Ahi + off : (tile == 1) ? Alo + off
              : (tile == 2) ? Bhi + off : Blo + off;
            cp_async16(dst, src);
        }
    };

    load_stage(0, 0); CP_COMMIT();
    load_stage(1, 1); CP_COMMIT();

    int slot = 0;
    for (int kt = 0; kt < NKT; kt++) {
        CP_WAIT(1);
        __syncthreads();
        if (kt + 2 < NKT) {
            int ns = slot + 2; if (ns >= 3) ns -= 3;
            load_stage(kt + 2, ns);
            CP_COMMIT();
        } else {
            CP_COMMIT();
        }

        const uint32_t bb = sbase + slot * STG_B;
#pragma unroll
        for (int ks = 0; ks < 2; ks++) {
            uint32_t ah[4][4], al[4][4];
#pragma unroll
            for (int mt = 0; mt < 4; mt++) {
                int row = wm + mt * 16 + (lane & 15);
                int c = ks * 2 + (lane >> 4);
                uint32_t so = sw64((uint32_t)(row * 64 + c * 16));
                ldm_x4(ah[mt], bb + 0 * STG_T + so);
                ldm_x4(al[mt], bb + 1 * STG_T + so);
            }
            // B frags: one ldm_x4 covers two adjacent n8 tiles
            uint32_t bh[4][2], bl[4][2];
#pragma unroll
            for (int np = 0; np < 2; np++) {
                int row = wn + np * 16 + (lane & 7) + ((lane >> 4) << 3);
                int c = ks * 2 + ((lane >> 3) & 1);
                uint32_t so = sw64((uint32_t)(row * 64 + c * 16));
                uint32_t r4[4];
                ldm_x4(r4, bb + 2 * STG_T + so);
                bh[np * 2][0] = r4[0]; bh[np * 2][1] = r4[1];
                bh[np * 2 + 1][0] = r4[2]; bh[np * 2 + 1][1] = r4[3];
                ldm_x4(r4, bb + 3 * STG_T + so);
                bl[np * 2][0] = r4[0]; bl[np * 2][1] = r4[1];
                bl[np * 2 + 1][0] = r4[2]; bl[np * 2 + 1][1] = r4[3];
            }
#pragma unroll
            for (int mt = 0; mt < 4; mt++)
#pragma unroll
                for (int nt = 0; nt < 4; nt++) {
                    mma_bf16(acc[mt][nt], ah[mt], bh[nt]);
                    mma_bf16(acc[mt][nt], ah[mt], bl[nt]);
                    mma_bf16(acc[mt][nt], al[mt], bh[nt]);
                }
        }
        if (++slot == 3) slot = 0;
    }

    const int g = lane >> 2, t = lane & 3;

    if (MODE == 0) {
        // ---- plain fp32 + bias ----
#pragma unroll
        for (int mt = 0; mt < 4; mt++) {
            int r0 = m0 + wm + mt * 16 + g;
#pragma unroll
            for (int nt = 0; nt < 4; nt++) {
                int col = n0 + wn + nt * 8 + t * 2;
                float2 bv = *(const float2*)&bias[col];
                float2 o0, o1;
                o0.x = acc[mt][nt][0] + bv.x;
                o0.y = acc[mt][nt][1] + bv.y;
                o1.x = acc[mt][nt][2] + bv.x;
                o1.y = acc[mt][nt][3] + bv.y;
                *(float2*)&C[(size_t)r0 * DM + col] = o0;
                *(float2*)&C[(size_t)(r0 + 8) * DM + col] = o1;
            }
        }
        return;
    }

    // ---- staged epilogues: tile -> smem fp32 [128][129] (reuse stages) ----
    __syncthreads();                       // all ldmatrix reads done
    float* csm = (float*)smraw;
#pragma unroll
    for (int mt = 0; mt < 4; mt++) {
        int r0 = wm + mt * 16 + g;
#pragma unroll
        for (int nt = 0; nt < 4; nt++) {
            int col = wn + nt * 8 + t * 2;
            float2 bv = *(const float2*)&bias[n0 + col];
            csm[r0 * 129 + col]           = acc[mt][nt][0] + bv.x;
            csm[r0 * 129 + col + 1]       = acc[mt][nt][1] + bv.y;
            csm[(r0 + 8) * 129 + col]     = acc[mt][nt][2] + bv.x;
            csm[(r0 + 8) * 129 + col + 1] = acc[mt][nt][3] + bv.y;
        }
    }
    __syncthreads();

    if (MODE == 1) {
        // ---- Vt: [(bh*64+d)][s] FP16 hi/lo, 4 consecutive s per thread ----
        __half* Fhi = (__half*)Dhi;
        __half* Flo = (__half*)Dlo;
#pragma unroll
        for (int i = 0; i < 16; i++) {
            int idx = i * 256 + tid;           // 0..4095 (chunks of 4 s)
            int drow = idx >> 5, s4 = (idx & 31) * 4;
            float v0 = csm[(s4 + 0) * 129 + drow];
            float v1 = csm[(s4 + 1) * 129 + drow];
            float v2 = csm[(s4 + 2) * 129 + drow];
            float v3 = csm[(s4 + 3) * 129 + drow];
            int m = m0 + s4, b = m >> 11, s = m & (SQ - 1);
            int ncol = n0 + drow, h = ncol >> 6, d = ncol & 63;
            size_t o = (size_t)((b * NH + h) * DKH + d) * SQ + s;
            float h0 = __half2float(__float2half_rn(v0));
            float h1 = __half2float(__float2half_rn(v1));
            float h2 = __half2float(__float2half_rn(v2));
            float h3 = __half2float(__float2half_rn(v3));
            uint2 hv, lv;
            hv.x = packh2(h0, h1); hv.y = packh2(h2, h3);
            lv.x = packh2(v0 - h0, v1 - h1);
            lv.y = packh2(v2 - h2, v3 - h3);
            *(uint2*)&Fhi[o] = hv;
            *(uint2*)&Flo[o] = lv;
        }
    } else {
        // ---- MODE 2: RoPE + (opt) scale + hi/lo split, 4 n per thread ----
        float sc = scaleQ ? 0.125f : 1.0f;
#pragma unroll
        for (int i = 0; i < 16; i++) {
            int idx = i * 256 + tid;           // 0..4095 (chunks of 4 n)
            int row = idx >> 5, n4 = (idx & 31) * 4;
            int d = n4 & 63, j = d & 31, hb = n4 & 64;
            int m = m0 + row, s = m & (SQ - 1);
            const float* cr = csm + row * 129 + hb;
            float r[4];
            bool first = (d < 32);
#pragma unroll
            for (int e = 0; e < 4; e++) {
                int jj = j + e;
                float x1 = cr[jj], x2 = cr[jj + 32];
                float2 cs = *(const float2*)&g_rope[2 * (s * 32 + jj)];
                r[e] = first ? (x1 * cs.x - x2 * cs.y)
                             : (x1 * cs.y + x2 * cs.x);
                r[e] *= sc;
            }
            float h0 = __bfloat162float(__float2bfloat16_rn(r[0]));
            float h1 = __bfloat162float(__float2bfloat16_rn(r[1]));
            float h2 = __bfloat162float(__float2bfloat16_rn(r[2]));
            float h3 = __bfloat162float(__float2bfloat16_rn(r[3]));
            uint2 hv, lv;
            hv.x = packbf2(h0, h1); hv.y = packbf2(h2, h3);
            lv.x = packbf2(r[0] - h0, r[1] - h1);
            lv.y = packbf2(r[2] - h2, r[3] - h3);
            size_t o = (size_t)m * DM + n0 + n4;
            *(uint2*)&Dhi[o] = hv;
            *(uint2*)&Dlo[o] = lv;
        }
    }
}

// ---------------------------------------------------------------------------
// Tensor-core flash attention; K frags pairwise ldm_x4.
// S-phase: bf16 3-MMA split. PV-phase: P single fp16, V fp16 hi/lo (2 MMAs).
// ---------------------------------------------------------------------------
#define FS_QH 0
#define FS_QL 16384
#define FS_ST 32768
#define FS_STB 32768
#define FA3_SMEM (FS_ST + 2 * FS_STB + 1024)

__global__ __launch_bounds__(256, 2) void flash_tc()
{
    extern __shared__ char smraw[];
    const uint32_t sb = (smem_u32(smraw) + 1023) & ~1023u;

    const int tid = threadIdx.x;
    const int wid = tid >> 5, lane = tid & 31;
    const int bh = blockIdx.y, b = bh >> 4, h = bh & 15;
    const int q0 = blockIdx.x * 128;

    const __nv_bfloat16* Qh = g_bf + BF_QHI + (size_t)(b * SQ + q0) * DM + h * DKH;
    const __nv_bfloat16* Ql = g_bf + BF_QLO + (size_t)(b * SQ + q0) * DM + h * DKH;
    const __nv_bfloat16* Kh = g_bf + BF_KHI + (size_t)(b * SQ) * DM + h * DKH;
    const __nv_bfloat16* Kl = g_bf + BF_KLO + (size_t)(b * SQ) * DM + h * DKH;
    const __half* Vh = (const __half*)(g_bf + BF_VTHI) + (size_t)(bh * DKH) * SQ;
    const __half* Vl = (const __half*)(g_bf + BF_VTLO) + (size_t)(bh * DKH) * SQ;

#pragma unroll
    for (int it = 0; it < 8; it++) {
        int i = it * 256 + tid;            // 0..2047
        int arr = i >> 10, idx = i & 1023;
        int row = idx >> 3, c8 = idx & 7;
        const __nv_bfloat16* src = (arr ? Ql : Qh) + (size_t)row * DM + c8 * 8;
        uint32_t dst = sb + (arr ? FS_QL : FS_QH)
                     + sw128((uint32_t)(row * 128 + c8 * 16));
        cp_async16(dst, src);
    }
    CP_COMMIT();

    auto load_stage = [&](int ktile, int buf) {
        const uint32_t bb = sb + FS_ST + buf * FS_STB;
#pragma unroll
        for (int it = 0; it < 8; it++) {
            int i = it * 256 + tid;        // 0..2047
            int tile = i >> 9, idx = i & 511;
            int row = idx >> 3, c8 = idx & 7;
            const void* src;
            if (tile < 2) {
                src = (tile ? Kl : Kh)
                    + (size_t)(ktile * 64 + row) * DM + c8 * 8;
            } else {
                src = ((tile == 3) ? Vl : Vh)
                    + (size_t)row * SQ + ktile * 64 + c8 * 8;
            }
            uint32_t dst = bb + (tile << 13)
                         + sw128((uint32_t)(row * 128 + c8 * 16));
            cp_async16(dst, src);
        }
    };

    load_stage(0, 0);
    CP_COMMIT();
    CP_WAIT(1);                // Q arrived
    __syncthreads();

    uint32_t qh[4][4], ql[4][4];
#pragma unroll
    for (int kt = 0; kt < 4; kt++) {
        int row = wid * 16 + (lane & 15);
        uint32_t so = sw128((uint32_t)(row * 128 + kt * 32 + (lane >> 4) * 16));
        ldm_x4(qh[kt], sb + FS_QH + so);
        ldm_x4(ql[kt], sb + FS_QL + so);
    }

    float m_i[2] = {-1e30f, -1e30f};
    float l_i[2] = {0.f, 0.f};
    float o[8][4];
#pragma unroll
    for (int nt = 0; nt < 8; nt++)
#pragma unroll
        for (int r = 0; r < 4; r++) o[nt][r] = 0.f;

    for (int ktile = 0; ktile < SQ / 64; ktile++) {
        const int buf = ktile & 1;
        if (ktile < SQ / 64 - 1) {
            load_stage(ktile + 1, buf ^ 1);
            CP_COMMIT();
            CP_WAIT(1);
        } else {
            CP_WAIT(0);
        }
        __syncthreads();

        const uint32_t bb = sb + FS_ST + buf * FS_STB;
        const uint32_t KH = bb, KL = bb + 8192, VH = bb + 16384, VL = bb + 24576;

        float sacc[8][4];
#pragma unroll
        for (int nt = 0; nt < 8; nt++)
#pragma unroll
            for (int r = 0; r < 4; r++) sacc[nt][r] = 0.f;

#pragma unroll
        for (int kt = 0; kt < 4; kt++) {
            uint32_t bhf[8][2], blf[8][2];
#pragma unroll
            for (int np = 0; np < 4; np++) {
                int row = np * 16 + (lane & 7) + ((lane >> 4) << 3);
                uint32_t so = sw128((uint32_t)(row * 128 + kt * 32
                                               + ((lane >> 3) & 1) * 16));
                uint32_t r4[4];
                ldm_x4(r4, KH + so);
                bhf[np * 2][0] = r4[0]; bhf[np * 2][1] = r4[1];
                bhf[np * 2 + 1][0] = r4[2]; bhf[np * 2 + 1][1] = r4[3];
                ldm_x4(r4, KL + so);
                blf[np * 2][0] = r4[0]; blf[np * 2][1] = r4[1];
                blf[np * 2 + 1][0] = r4[2]; blf[np * 2 + 1][1] = r4[3];
            }
#pragma unroll
            for (int nt = 0; nt < 8; nt++) {
                mma_bf16(sacc[nt], qh[kt], bhf[nt]);
                mma_bf16(sacc[nt], qh[kt], blf[nt]);
                mma_bf16(sacc[nt], ql[kt], bhf[nt]);
            }
        }

        float mx0 = -1e30f, mx1 = -1e30f;
#pragma unroll
        for (int nt = 0; nt < 8; nt++) {
            mx0 = fmaxf(mx0, fmaxf(sacc[nt][0], sacc[nt][1]));
            mx1 = fmaxf(mx1, fmaxf(sacc[nt][2], sacc[nt][3]));
        }
        mx0 = fmaxf(mx0, __shfl_xor_sync(0xffffffffu, mx0, 1));
        mx0 = fmaxf(mx0, __shfl_xor_sync(0xffffffffu, mx0, 2));
        mx1 = fmaxf(mx1, __shfl_xor_sync(0xffffffffu, mx1, 1));
        mx1 = fmaxf(mx1, __shfl_xor_sync(0xffffffffu, mx1, 2));
        float mn0 = fmaxf(m_i[0], mx0), mn1 = fmaxf(m_i[1], mx1);
        float al0 = __expf(m_i[0] - mn0), al1 = __expf(m_i[1] - mn1);
        float rs0 = 0.f, rs1 = 0.f;
#pragma unroll
        for (int nt = 0; nt < 8; nt++) {
            sacc[nt][0] = __expf(sacc[nt][0] - mn0);
            sacc[nt][1] = __expf(sacc[nt][1] - mn0);
            sacc[nt][2] = __expf(sacc[nt][2] - mn1);
            sacc[nt][3] = __expf(sacc[nt][3] - mn1);
            rs0 += sacc[nt][0] + sacc[nt][1];
            rs1 += sacc[nt][2] + sacc[nt][3];
        }
        rs0 += __shfl_xor_sync(0xffffffffu, rs0, 1);
        rs0 += __shfl_xor_sync(0xffffffffu, rs0, 2);
        rs1 += __shfl_xor_sync(0xffffffffu, rs1, 1);
        rs1 += __shfl_xor_sync(0xffffffffu, rs1, 2);
        l_i[0] = l_i[0] * al0 + rs0;
        l_i[1] = l_i[1] * al1 + rs1;
        m_i[0] = mn0; m_i[1] = mn1;
#pragma unroll
        for (int nt = 0; nt < 8; nt++) {
            o[nt][0] *= al0; o[nt][1] *= al0;
            o[nt][2] *= al1; o[nt][3] *= al1;
        }

        // ---- PV: P single fp16, V fp16 hi/lo (2 MMAs per pair) ----
#pragma unroll
        for (int t = 0; t < 4; t++) {
            uint32_t ahf[4];
            ahf[0] = packh2(sacc[2 * t][0], sacc[2 * t][1]);
            ahf[1] = packh2(sacc[2 * t][2], sacc[2 * t][3]);
            ahf[2] = packh2(sacc[2 * t + 1][0], sacc[2 * t + 1][1]);
            ahf[3] = packh2(sacc[2 * t + 1][2], sacc[2 * t + 1][3]);
#pragma unroll
            for (int np = 0; np < 4; np++) {
                uint32_t r4[4], vh0[2], vh1[2], vl0[2], vl1[2];
                int row = np * 16 + (lane & 7) + ((lane >> 4) << 3);
                uint32_t so = sw128((uint32_t)(row * 128 + t * 32
                                               + ((lane >> 3) & 1) * 16));
                ldm_x4(r4, VH + so);
                vh0[0] = r4[0]; vh0[1] = r4[1]; vh1[0] = r4[2]; vh1[1] = r4[3];
                ldm_x4(r4, VL + so);
                vl0[0] = r4[0]; vl0[1] = r4[1]; vl1[0] = r4[2]; vl1[1] = r4[3];
                mma_f16(o[np * 2], ahf, vh0);
                mma_f16(o[np * 2], ahf, vl0);
                mma_f16(o[np * 2 + 1], ahf, vh1);
                mma_f16(o[np * 2 + 1], ahf, vl1);
            }
        }
        __syncthreads();
    }

    // ---- epilogue: divide by l, bf16 hi/lo split, store a_hi/a_lo ----
    float inv0 = 1.f / l_i[0], inv1 = 1.f / l_i[1];
    int r0 = q0 + wid * 16 + (lane >> 2);
    __nv_bfloat16* Ah = g_bf + BF_AHI + (size_t)(b * SQ) * DM + h * DKH;
    __nv_bfloat16* Al = g_bf + BF_ALO + (size_t)(b * SQ) * DM + h * DKH;
#pragma unroll
    for (int nt = 0; nt < 8; nt++) {
        int col = nt * 8 + (lane & 3) * 2;
        float a0 = o[nt][0] * inv0, a1 = o[nt][1] * inv0;
        float a2 = o[nt][2] * inv1, a3 = o[nt][3] * inv1;
        float h0 = __bfloat162float(__float2bfloat16_rn(a0));
        float h1 = __bfloat162float(__float2bfloat16_rn(a1));
        float h2 = __bfloat162float(__float2bfloat16_rn(a2));
        float h3 = __bfloat162float(__float2bfloat16_rn(a3));
        *(uint32_t*)&Ah[(size_t)r0 * DM + col]       = packbf2(h0, h1);
        *(uint32_t*)&Al[(size_t)r0 * DM + col]       = packbf2(a0 - h0, a1 - h1);
        *(uint32_t*)&Ah[(size_t)(r0 + 8) * DM + col] = packbf2(h2, h3);
        *(uint32_t*)&Al[(size_t)(r0 + 8) * DM + col] = packbf2(a2 - h2, a3 - h3);
    }
}

// ---------------------------------------------------------------------------
extern "C" void kernel_launch(void* const* d_in, const int* in_sizes, int n_in,
                              void* d_out, int out_size)
{
    const float* x  = (const float*)d_in[0];
    const float* Wq = (const float*)d_in[1];
    const float* bq = (const float*)d_in[2];
    const float* Wk = (const float*)d_in[3];
    const float* bk = (const float*)d_in[4];
    const float* Wv = (const float*)d_in[5];
    const float* bv = (const float*)d_in[6];
    const float* Wo = (const float*)d_in[7];
    const float* bo = (const float*)d_in[8];
    float* out = (float*)d_out;

    __nv_bfloat16* bf = nullptr;
    cudaGetSymbolAddress((void**)&bf, g_bf);

    cudaFuncSetAttribute(mm_gemm<0>,
                         cudaFuncAttributeMaxDynamicSharedMemorySize, MM_SMEM);
    cudaFuncSetAttribute(mm_gemm<1>,
                         cudaFuncAttributeMaxDynamicSharedMemorySize, MM_SMEM);
    cudaFuncSetAttribute(mm_gemm<2>,
                         cudaFuncAttributeMaxDynamicSharedMemorySize, MM_SMEM);
    cudaFuncSetAttribute(flash_tc,
                         cudaFuncAttributeMaxDynamicSharedMemorySize, FA3_SMEM);

    // 1) prep: rope table, x split, weight transpose+split
    rope_table_kernel<<<SQ * 32 / 256, 256>>>();
    split_kernel<<<MROWS * DM / 1024, 256>>>(x, bf + BF_XHI, bf + BF_XLO);
    wsplit_kernel<<<dim3(32, 32, 4), dim3(32, 8)>>>(Wq, Wk, Wv, Wo);

    // 2) Q/K/V projections with fused (vectorized) epilogues
    mm_gemm<2><<<dim3(8, 32), 256, MM_SMEM>>>(
        bf + BF_XHI, bf + BF_XLO,
        bf + BF_WT + 0ull * DM * DM, bf + BF_WT + 1ull * DM * DM, bq,
        nullptr, bf + BF_QHI, bf + BF_QLO, 1);
    mm_gemm<2><<<dim3(8, 32), 256, MM_SMEM>>>(
        bf + BF_XHI, bf + BF_XLO,
        bf + BF_WT + 2ull * DM * DM, bf + BF_WT + 3ull * DM * DM, bk,
        nullptr, bf + BF_KHI, bf + BF_KLO, 0);
    mm_gemm<1><<<dim3(8, 32), 256, MM_SMEM>>>(
        bf + BF_XHI, bf + BF_XLO,
        bf + BF_WT + 4ull * DM * DM, bf + BF_WT + 5ull * DM * DM, bv,
        nullptr, bf + BF_VTHI, bf + BF_VTLO, 0);

    // 3) Flash attention (fp16 PV; writes a_hi/a_lo bf16 directly)
    flash_tc<<<dim3(SQ / 128, NB * NH), 256, FA3_SMEM>>>();

    // 4) output projection (fp32 out)
    mm_gemm<0><<<dim3(8, 32), 256, MM_SMEM>>>(
        bf + BF_AHI, bf + BF_ALO,
        bf + BF_WT + 6ull * DM * DM, bf + BF_WT + 7ull * DM * DM, bo,
        out, nullptr, nullptr, 0);
}

// round 16
// speedup vs baseline: 1.2837x; 1.0715x over previous
#include <cuda_runtime.h>
#include <cuda_bf16.h>
#include <cuda_fp16.h>
#include <math.h>
#include <stdint.h>

#define SQ   2048
#define NB   2
#define NH   16
#define DKH  64
#define DM   1024
#define MROWS 4096   // NB*SQ

// ---------------------------------------------------------------------------
// Scratch (__device__ globals; allocation-free rule)
// ---------------------------------------------------------------------------
__device__ float g_rope[SQ * 32 * 2];                    // cos,sin per (s,j)

// 2-byte scratch offsets (elements; MROWS*DM = 4M, DM*DM = 1M)
#define BF_XHI  0ull
#define BF_XLO  (1ull * MROWS * DM)
#define BF_WT   (2ull * MROWS * DM)                       // 8 x DM*DM
#define BF_AHI  (BF_WT + 8ull * DM * DM)
#define BF_ALO  (BF_AHI + 1ull * MROWS * DM)
#define BF_QHI  (BF_ALO + 1ull * MROWS * DM)              // fp16 payload
#define BF_QLO  (BF_QHI + 1ull * MROWS * DM)              // fp16 payload
#define BF_KHI  (BF_QLO + 1ull * MROWS * DM)              // fp16 payload (single)
#define BF_KLO  (BF_KHI + 1ull * MROWS * DM)              // unused now
#define BF_VTHI (BF_KLO + 1ull * MROWS * DM)              // fp16 payload
#define BF_VTLO (BF_VTHI + 1ull * MROWS * DM)             // fp16 payload
__device__ __nv_bfloat16 g_bf[BF_VTLO + 1ull * MROWS * DM];

// ---------------------------------------------------------------------------
// Helpers (sm_100-safe: cp.async, ldmatrix, mma.sync only)
// ---------------------------------------------------------------------------
__device__ __forceinline__ uint32_t smem_u32(const void* p) {
    uint32_t a;
    asm("{ .reg .u64 t; cvta.to.shared.u64 t, %1; cvt.u32.u64 %0, t; }"
        : "=r"(a) : "l"(p));
    return a;
}

__device__ __forceinline__ uint32_t sw64(uint32_t off) {
    return off ^ ((off >> 3) & 0x30);
}
__device__ __forceinline__ uint32_t sw128(uint32_t off) {
    return off ^ ((off >> 3) & 0x70);
}

__device__ __forceinline__ void ldm_x4(uint32_t* r, uint32_t addr) {
    asm volatile("ldmatrix.sync.aligned.m8n8.x4.shared.b16 {%0,%1,%2,%3}, [%4];"
                 : "=r"(r[0]), "=r"(r[1]), "=r"(r[2]), "=r"(r[3]) : "r"(addr));
}

__device__ __forceinline__ void mma_bf16(float* d, const uint32_t* a,
                                         const uint32_t* b) {
    asm volatile(
        "mma.sync.aligned.m16n8k16.row.col.f32.bf16.bf16.f32 "
        "{%0,%1,%2,%3}, {%4,%5,%6,%7}, {%8,%9}, {%0,%1,%2,%3};"
        : "+f"(d[0]), "+f"(d[1]), "+f"(d[2]), "+f"(d[3])
        : "r"(a[0]), "r"(a[1]), "r"(a[2]), "r"(a[3]), "r"(b[0]), "r"(b[1]));
}

__device__ __forceinline__ void mma_f16(float* d, const uint32_t* a,
                                        const uint32_t* b) {
    asm volatile(
        "mma.sync.aligned.m16n8k16.row.col.f32.f16.f16.f32 "
        "{%0,%1,%2,%3}, {%4,%5,%6,%7}, {%8,%9}, {%0,%1,%2,%3};"
        : "+f"(d[0]), "+f"(d[1]), "+f"(d[2]), "+f"(d[3])
        : "r"(a[0]), "r"(a[1]), "r"(a[2]), "r"(a[3]), "r"(b[0]), "r"(b[1]));
}

__device__ __forceinline__ void cp_async16(uint32_t dst, const void* src) {
    asm volatile("cp.async.cg.shared.global [%0], [%1], 16;"
                 :: "r"(dst), "l"(src));
}
#define CP_COMMIT() asm volatile("cp.async.commit_group;" ::: "memory")
#define CP_WAIT(n)  asm volatile("cp.async.wait_group %0;" :: "n"(n) : "memory")

__device__ __forceinline__ uint32_t packbf2(float a, float b) {
    __nv_bfloat162 t = __floats2bfloat162_rn(a, b);
    return *(uint32_t*)&t;
}
__device__ __forceinline__ uint32_t packh2(float a, float b) {
    __half2 t = __floats2half2_rn(a, b);
    return *(uint32_t*)&t;
}

// ---------------------------------------------------------------------------
// Prep: fp32 -> (bf16 hi, bf16 lo) split, 4 elems/thread
// ---------------------------------------------------------------------------
__global__ __launch_bounds__(256) void split_kernel(
    const float* __restrict__ src, __nv_bfloat16* __restrict__ hi,
    __nv_bfloat16* __restrict__ lo)
{
    size_t i = (size_t)(blockIdx.x * 256 + threadIdx.x) * 4;
    float4 v = *(const float4*)(src + i);
    __nv_bfloat16 h0 = __float2bfloat16_rn(v.x);
    __nv_bfloat16 h1 = __float2bfloat16_rn(v.y);
    __nv_bfloat16 h2 = __float2bfloat16_rn(v.z);
    __nv_bfloat16 h3 = __float2bfloat16_rn(v.w);
    __nv_bfloat16 l0 = __float2bfloat16_rn(v.x - __bfloat162float(h0));
    __nv_bfloat16 l1 = __float2bfloat16_rn(v.y - __bfloat162float(h1));
    __nv_bfloat16 l2 = __float2bfloat16_rn(v.z - __bfloat162float(h2));
    __nv_bfloat16 l3 = __float2bfloat16_rn(v.w - __bfloat162float(h3));
    ((__nv_bfloat162*)(hi + i))[0] = __nv_bfloat162(h0, h1);
    ((__nv_bfloat162*)(hi + i))[1] = __nv_bfloat162(h2, h3);
    ((__nv_bfloat162*)(lo + i))[0] = __nv_bfloat162(l0, l1);
    ((__nv_bfloat162*)(lo + i))[1] = __nv_bfloat162(l2, l3);
}

// ---------------------------------------------------------------------------
// Prep: transpose + split the 4 weight matrices W[k][n] -> Wt_hi/lo[n][k]
// ---------------------------------------------------------------------------
__global__ __launch_bounds__(256) void wsplit_kernel(
    const float* __restrict__ W0, const float* __restrict__ W1,
    const float* __restrict__ W2, const float* __restrict__ W3)
{
    __shared__ float t[32][33];
    const float* W = (blockIdx.z == 0) ? W0 : (blockIdx.z == 1) ? W1
                   : (blockIdx.z == 2) ? W2 : W3;
    __nv_bfloat16* whi = g_bf + BF_WT + (size_t)(2 * blockIdx.z) * DM * DM;
    __nv_bfloat16* wlo = whi + (size_t)DM * DM;
    int tx = threadIdx.x, ty = threadIdx.y;
    int n = blockIdx.x * 32 + tx;
#pragma unroll
    for (int i = 0; i < 32; i += 8)
        t[ty + i][tx] = W[(size_t)(blockIdx.y * 32 + ty + i) * DM + n];
    __syncthreads();
#pragma unroll
    for (int i = 0; i < 32; i += 8) {
        float v = t[tx][ty + i];
        __nv_bfloat16 h = __float2bfloat16_rn(v);
        __nv_bfloat16 l = __float2bfloat16_rn(v - __bfloat162float(h));
        size_t o = (size_t)(blockIdx.x * 32 + ty + i) * DM + blockIdx.y * 32 + tx;
        whi[o] = h;
        wlo[o] = l;
    }
}

// ---------------------------------------------------------------------------
// RoPE cos/sin table: (s, j) -> g_rope[2*(s*32+j)] = {cos, sin}
// ---------------------------------------------------------------------------
__global__ __launch_bounds__(256) void rope_table_kernel()
{
    int i = blockIdx.x * 256 + threadIdx.x;   // 0 .. 65535
    int s = i >> 5, j = i & 31;
    float invf = (float)pow(10000.0, -(double)j / 32.0);
    float ang = (float)s * invf;
    float sn, c;
    sincosf(ang, &sn, &c);
    g_rope[2 * i]     = c;
    g_rope[2 * i + 1] = sn;
}

// ---------------------------------------------------------------------------
// mma.sync bf16-split GEMM, 3-stage cp.async pipeline, fused epilogues.
// MODE 0: C = acc + bias (fp32, row-major)
// MODE 1: Vt hi/lo FP16, transposed write [(bh*64+d)][s]  (vectorized x4)
// MODE 2: RoPE + split. scaleQ=1: Q fp16 hi/lo (0.125 scale);
//                       scaleQ=0: K single fp16.
// ---------------------------------------------------------------------------
#define KCH 32
#define NKT (DM / KCH)             // 32 chunks
#define STG_T 8192
#define STG_B (4 * STG_T)          // 32 KB per stage
#define MM_SMEM (3 * STG_B + 1024)

template <int MODE>
__global__ __launch_bounds__(256, 2) void mm_gemm(
    const __nv_bfloat16* __restrict__ Ahi, const __nv_bfloat16* __restrict__ Alo,
    const __nv_bfloat16* __restrict__ Bhi, const __nv_bfloat16* __restrict__ Blo,
    const float* __restrict__ bias, float* __restrict__ C,
    __nv_bfloat16* __restrict__ Dhi, __nv_bfloat16* __restrict__ Dlo,
    int scaleQ)
{
    extern __shared__ char smraw[];
    const uint32_t sbase = (smem_u32(smraw) + 1023) & ~1023u;

    const int tid  = threadIdx.x;
    const int wid  = tid >> 5, lane = tid & 31;
    const int m0   = blockIdx.y * 128, n0 = blockIdx.x * 128;
    const int wm   = (wid >> 2) * 64, wn = (wid & 3) * 32;

    float acc[4][4][4];
#pragma unroll
    for (int i = 0; i < 4; i++)
#pragma unroll
        for (int j = 0; j < 4; j++)
#pragma unroll
            for (int r = 0; r < 4; r++) acc[i][j][r] = 0.f;

    auto load_stage = [&](int kt, int slot) {
        const uint32_t bb = sbase + slot * STG_B;
#pragma unroll
        for (int it = 0; it < 8; it++) {
            int i = it * 256 + tid;
            int tile = i >> 9, idx = i & 511;
            int r = idx >> 2, c = idx & 3;
            uint32_t dst = bb + tile * STG_T + sw64((uint32_t)(r * 64 + c * 16));
            size_t off = (tile < 2)
                ? (size_t)(m0 + r) * DM + kt * KCH + c * 8
                : (size_t)(n0 + r) * DM + kt * KCH + c * 8;
            const __nv_bfloat16* src =
                (tile == 0) ? Ahi + off : (tile == 1) ? Alo + off
              : (tile == 2) ? Bhi + off : Blo + off;
            cp_async16(dst, src);
        }
    };

    load_stage(0, 0); CP_COMMIT();
    load_stage(1, 1); CP_COMMIT();

    int slot = 0;
    for (int kt = 0; kt < NKT; kt++) {
        CP_WAIT(1);
        __syncthreads();
        if (kt + 2 < NKT) {
            int ns = slot + 2; if (ns >= 3) ns -= 3;
            load_stage(kt + 2, ns);
            CP_COMMIT();
        } else {
            CP_COMMIT();
        }

        const uint32_t bb = sbase + slot * STG_B;
#pragma unroll
        for (int ks = 0; ks < 2; ks++) {
            uint32_t ah[4][4], al[4][4];
#pragma unroll
            for (int mt = 0; mt < 4; mt++) {
                int row = wm + mt * 16 + (lane & 15);
                int c = ks * 2 + (lane >> 4);
                uint32_t so = sw64((uint32_t)(row * 64 + c * 16));
                ldm_x4(ah[mt], bb + 0 * STG_T + so);
                ldm_x4(al[mt], bb + 1 * STG_T + so);
            }
            uint32_t bh[4][2], bl[4][2];
#pragma unroll
            for (int np = 0; np < 2; np++) {
                int row = wn + np * 16 + (lane & 7) + ((lane >> 4) << 3);
                int c = ks * 2 + ((lane >> 3) & 1);
                uint32_t so = sw64((uint32_t)(row * 64 + c * 16));
                uint32_t r4[4];
                ldm_x4(r4, bb + 2 * STG_T + so);
                bh[np * 2][0] = r4[0]; bh[np * 2][1] = r4[1];
                bh[np * 2 + 1][0] = r4[2]; bh[np * 2 + 1][1] = r4[3];
                ldm_x4(r4, bb + 3 * STG_T + so);
                bl[np * 2][0] = r4[0]; bl[np * 2][1] = r4[1];
                bl[np * 2 + 1][0] = r4[2]; bl[np * 2 + 1][1] = r4[3];
            }
#pragma unroll
            for (int mt = 0; mt < 4; mt++)
#pragma unroll
                for (int nt = 0; nt < 4; nt++) {
                    mma_bf16(acc[mt][nt], ah[mt], bh[nt]);
                    mma_bf16(acc[mt][nt], ah[mt], bl[nt]);
                    mma_bf16(acc[mt][nt], al[mt], bh[nt]);
                }
        }
        if (++slot == 3) slot = 0;
    }

    const int g = lane >> 2, t = lane & 3;

    if (MODE == 0) {
#pragma unroll
        for (int mt = 0; mt < 4; mt++) {
            int r0 = m0 + wm + mt * 16 + g;
#pragma unroll
            for (int nt = 0; nt < 4; nt++) {
                int col = n0 + wn + nt * 8 + t * 2;
                float2 bv = *(const float2*)&bias[col];
                float2 o0, o1;
                o0.x = acc[mt][nt][0] + bv.x;
                o0.y = acc[mt][nt][1] + bv.y;
                o1.x = acc[mt][nt][2] + bv.x;
                o1.y = acc[mt][nt][3] + bv.y;
                *(float2*)&C[(size_t)r0 * DM + col] = o0;
                *(float2*)&C[(size_t)(r0 + 8) * DM + col] = o1;
            }
        }
        return;
    }

    // ---- staged epilogues: tile -> smem fp32 [128][129] (reuse stages) ----
    __syncthreads();
    float* csm = (float*)smraw;
#pragma unroll
    for (int mt = 0; mt < 4; mt++) {
        int r0 = wm + mt * 16 + g;
#pragma unroll
        for (int nt = 0; nt < 4; nt++) {
            int col = wn + nt * 8 + t * 2;
            float2 bv = *(const float2*)&bias[n0 + col];
            csm[r0 * 129 + col]           = acc[mt][nt][0] + bv.x;
            csm[r0 * 129 + col + 1]       = acc[mt][nt][1] + bv.y;
            csm[(r0 + 8) * 129 + col]     = acc[mt][nt][2] + bv.x;
            csm[(r0 + 8) * 129 + col + 1] = acc[mt][nt][3] + bv.y;
        }
    }
    __syncthreads();

    if (MODE == 1) {
        // ---- Vt: [(bh*64+d)][s] FP16 hi/lo ----
        __half* Fhi = (__half*)Dhi;
        __half* Flo = (__half*)Dlo;
#pragma unroll
        for (int i = 0; i < 16; i++) {
            int idx = i * 256 + tid;
            int drow = idx >> 5, s4 = (idx & 31) * 4;
            float v0 = csm[(s4 + 0) * 129 + drow];
            float v1 = csm[(s4 + 1) * 129 + drow];
            float v2 = csm[(s4 + 2) * 129 + drow];
            float v3 = csm[(s4 + 3) * 129 + drow];
            int m = m0 + s4, b = m >> 11, s = m & (SQ - 1);
            int ncol = n0 + drow, h = ncol >> 6, d = ncol & 63;
            size_t o = (size_t)((b * NH + h) * DKH + d) * SQ + s;
            float h0 = __half2float(__float2half_rn(v0));
            float h1 = __half2float(__float2half_rn(v1));
            float h2 = __half2float(__float2half_rn(v2));
            float h3 = __half2float(__float2half_rn(v3));
            uint2 hv, lv;
            hv.x = packh2(h0, h1); hv.y = packh2(h2, h3);
            lv.x = packh2(v0 - h0, v1 - h1);
            lv.y = packh2(v2 - h2, v3 - h3);
            *(uint2*)&Fhi[o] = hv;
            *(uint2*)&Flo[o] = lv;
        }
    } else {
        // ---- MODE 2: RoPE + split to fp16 ----
        __half* Fhi = (__half*)Dhi;
        __half* Flo = (__half*)Dlo;
        float sc = scaleQ ? 0.125f : 1.0f;
#pragma unroll
        for (int i = 0; i < 16; i++) {
            int idx = i * 256 + tid;
            int row = idx >> 5, n4 = (idx & 31) * 4;
            int d = n4 & 63, j = d & 31, hb = n4 & 64;
            int m = m0 + row, s = m & (SQ - 1);
            const float* cr = csm + row * 129 + hb;
            float r[4];
            bool first = (d < 32);
#pragma unroll
            for (int e = 0; e < 4; e++) {
                int jj = j + e;
                float x1 = cr[jj], x2 = cr[jj + 32];
                float2 cs = *(const float2*)&g_rope[2 * (s * 32 + jj)];
                r[e] = first ? (x1 * cs.x - x2 * cs.y)
                             : (x1 * cs.y + x2 * cs.x);
                r[e] *= sc;
            }
            size_t o = (size_t)m * DM + n0 + n4;
            if (scaleQ) {
                // Q: fp16 hi/lo split
                float h0 = __half2float(__float2half_rn(r[0]));
                float h1 = __half2float(__float2half_rn(r[1]));
                float h2 = __half2float(__float2half_rn(r[2]));
                float h3 = __half2float(__float2half_rn(r[3]));
                uint2 hv, lv;
                hv.x = packh2(h0, h1); hv.y = packh2(h2, h3);
                lv.x = packh2(r[0] - h0, r[1] - h1);
                lv.y = packh2(r[2] - h2, r[3] - h3);
                *(uint2*)&Fhi[o] = hv;
                *(uint2*)&Flo[o] = lv;
            } else {
                // K: single fp16
                uint2 hv;
                hv.x = packh2(r[0], r[1]); hv.y = packh2(r[2], r[3]);
                *(uint2*)&Fhi[o] = hv;
            }
        }
    }
}

// ---------------------------------------------------------------------------
// Tensor-core flash attention.
// S-phase: Q fp16 hi/lo x K single fp16 (2 MMAs). Softmax in regs.
// PV-phase: P single fp16 x V fp16 hi/lo (2 MMAs).
// Stage: K (8KB) + VH (8KB) + VL (8KB) = 24KB, double buffered.
// ---------------------------------------------------------------------------
#define FS_QH 0
#define FS_QL 16384
#define FS_ST 32768
#define FS_STB 24576
#define FA3_SMEM (FS_ST + 2 * FS_STB + 1024)

__global__ __launch_bounds__(256, 2) void flash_tc()
{
    extern __shared__ char smraw[];
    const uint32_t sb = (smem_u32(smraw) + 1023) & ~1023u;

    const int tid = threadIdx.x;
    const int wid = tid >> 5, lane = tid & 31;
    const int bh = blockIdx.y, b = bh >> 4, h = bh & 15;
    const int q0 = blockIdx.x * 128;

    const __half* Qh = (const __half*)(g_bf + BF_QHI) + (size_t)(b * SQ + q0) * DM + h * DKH;
    const __half* Ql = (const __half*)(g_bf + BF_QLO) + (size_t)(b * SQ + q0) * DM + h * DKH;
    const __half* Kh = (const __half*)(g_bf + BF_KHI) + (size_t)(b * SQ) * DM + h * DKH;
    const __half* Vh = (const __half*)(g_bf + BF_VTHI) + (size_t)(bh * DKH) * SQ;
    const __half* Vl = (const __half*)(g_bf + BF_VTLO) + (size_t)(bh * DKH) * SQ;

#pragma unroll
    for (int it = 0; it < 8; it++) {
        int i = it * 256 + tid;            // 0..2047
        int arr = i >> 10, idx = i & 1023;
        int row = idx >> 3, c8 = idx & 7;
        const __half* src = (arr ? Ql : Qh) + (size_t)row * DM + c8 * 8;
        uint32_t dst = sb + (arr ? FS_QL : FS_QH)
                     + sw128((uint32_t)(row * 128 + c8 * 16));
        cp_async16(dst, src);
    }
    CP_COMMIT();

    auto load_stage = [&](int ktile, int buf) {
        const uint32_t bb = sb + FS_ST + buf * FS_STB;
#pragma unroll
        for (int it = 0; it < 6; it++) {
            int i = it * 256 + tid;        // 0..1535
            int tile = i >> 9, idx = i & 511;
            int row = idx >> 3, c8 = idx & 7;
            const __half* src;
            if (tile == 0) {
                src = Kh + (size_t)(ktile * 64 + row) * DM + c8 * 8;
            } else {
                src = ((tile == 2) ? Vl : Vh)
                    + (size_t)row * SQ + ktile * 64 + c8 * 8;
            }
            uint32_t dst = bb + (tile << 13)
                         + sw128((uint32_t)(row * 128 + c8 * 16));
            cp_async16(dst, src);
        }
    };

    load_stage(0, 0);
    CP_COMMIT();
    CP_WAIT(1);                // Q arrived
    __syncthreads();

    uint32_t qh[4][4], ql[4][4];
#pragma unroll
    for (int kt = 0; kt < 4; kt++) {
        int row = wid * 16 + (lane & 15);
        uint32_t so = sw128((uint32_t)(row * 128 + kt * 32 + (lane >> 4) * 16));
        ldm_x4(qh[kt], sb + FS_QH + so);
        ldm_x4(ql[kt], sb + FS_QL + so);
    }

    float m_i[2] = {-1e30f, -1e30f};
    float l_i[2] = {0.f, 0.f};
    float o[8][4];
#pragma unroll
    for (int nt = 0; nt < 8; nt++)
#pragma unroll
        for (int r = 0; r < 4; r++) o[nt][r] = 0.f;

    for (int ktile = 0; ktile < SQ / 64; ktile++) {
        const int buf = ktile & 1;
        if (ktile < SQ / 64 - 1) {
            load_stage(ktile + 1, buf ^ 1);
            CP_COMMIT();
            CP_WAIT(1);
        } else {
            CP_WAIT(0);
        }
        __syncthreads();

        const uint32_t bb = sb + FS_ST + buf * FS_STB;
        const uint32_t KH = bb, VH = bb + 8192, VL = bb + 16384;

        // ---- S = Q K^T : Q fp16 hi/lo x K single fp16, 2 MMAs ----
        float sacc[8][4];
#pragma unroll
        for (int nt = 0; nt < 8; nt++)
#pragma unroll
            for (int r = 0; r < 4; r++) sacc[nt][r] = 0.f;

#pragma unroll
        for (int kt = 0; kt < 4; kt++) {
            uint32_t khf[8][2];
#pragma unroll
            for (int np = 0; np < 4; np++) {
                int row = np * 16 + (lane & 7) + ((lane >> 4) << 3);
                uint32_t so = sw128((uint32_t)(row * 128 + kt * 32
                                               + ((lane >> 3) & 1) * 16));
                uint32_t r4[4];
                ldm_x4(r4, KH + so);
                khf[np * 2][0] = r4[0]; khf[np * 2][1] = r4[1];
                khf[np * 2 + 1][0] = r4[2]; khf[np * 2 + 1][1] = r4[3];
            }
#pragma unroll
            for (int nt = 0; nt < 8; nt++) {
                mma_f16(sacc[nt], qh[kt], khf[nt]);
                mma_f16(sacc[nt], ql[kt], khf[nt]);
            }
        }

        float mx0 = -1e30f, mx1 = -1e30f;
#pragma unroll
        for (int nt = 0; nt < 8; nt++) {
            mx0 = fmaxf(mx0, fmaxf(sacc[nt][0], sacc[nt][1]));
            mx1 = fmaxf(mx1, fmaxf(sacc[nt][2], sacc[nt][3]));
        }
        mx0 = fmaxf(mx0, __shfl_xor_sync(0xffffffffu, mx0, 1));
        mx0 = fmaxf(mx0, __shfl_xor_sync(0xffffffffu, mx0, 2));
        mx1 = fmaxf(mx1, __shfl_xor_sync(0xffffffffu, mx1, 1));
        mx1 = fmaxf(mx1, __shfl_xor_sync(0xffffffffu, mx1, 2));
        float mn0 = fmaxf(m_i[0], mx0), mn1 = fmaxf(m_i[1], mx1);
        float al0 = __expf(m_i[0] - mn0), al1 = __expf(m_i[1] - mn1);
        float rs0 = 0.f, rs1 = 0.f;
#pragma unroll
        for (int nt = 0; nt < 8; nt++) {
            sacc[nt][0] = __expf(sacc[nt][0] - mn0);
            sacc[nt][1] = __expf(sacc[nt][1] - mn0);
            sacc[nt][2] = __expf(sacc[nt][2] - mn1);
            sacc[nt][3] = __expf(sacc[nt][3] - mn1);
            rs0 += sacc[nt][0] + sacc[nt][1];
            rs1 += sacc[nt][2] + sacc[nt][3];
        }
        rs0 += __shfl_xor_sync(0xffffffffu, rs0, 1);
        rs0 += __shfl_xor_sync(0xffffffffu, rs0, 2);
        rs1 += __shfl_xor_sync(0xffffffffu, rs1, 1);
        rs1 += __shfl_xor_sync(0xffffffffu, rs1, 2);
        l_i[0] = l_i[0] * al0 + rs0;
        l_i[1] = l_i[1] * al1 + rs1;
        m_i[0] = mn0; m_i[1] = mn1;
#pragma unroll
        for (int nt = 0; nt < 8; nt++) {
            o[nt][0] *= al0; o[nt][1] *= al0;
            o[nt][2] *= al1; o[nt][3] *= al1;
        }

        // ---- PV: P single fp16, V fp16 hi/lo (2 MMAs per pair) ----
#pragma unroll
        for (int t = 0; t < 4; t++) {
            uint32_t ahf[4];
            ahf[0] = packh2(sacc[2 * t][0], sacc[2 * t][1]);
            ahf[1] = packh2(sacc[2 * t][2], sacc[2 * t][3]);
            ahf[2] = packh2(sacc[2 * t + 1][0], sacc[2 * t + 1][1]);
            ahf[3] = packh2(sacc[2 * t + 1][2], sacc[2 * t + 1][3]);
#pragma unroll
            for (int np = 0; np < 4; np++) {
                uint32_t r4[4], vh0[2], vh1[2], vl0[2], vl1[2];
                int row = np * 16 + (lane & 7) + ((lane >> 4) << 3);
                uint32_t so = sw128((uint32_t)(row * 128 + t * 32
                                               + ((lane >> 3) & 1) * 16));
                ldm_x4(r4, VH + so);
                vh0[0] = r4[0]; vh0[1] = r4[1]; vh1[0] = r4[2]; vh1[1] = r4[3];
                ldm_x4(r4, VL + so);
                vl0[0] = r4[0]; vl0[1] = r4[1]; vl1[0] = r4[2]; vl1[1] = r4[3];
                mma_f16(o[np * 2], ahf, vh0);
                mma_f16(o[np * 2], ahf, vl0);
                mma_f16(o[np * 2 + 1], ahf, vh1);
                mma_f16(o[np * 2 + 1], ahf, vl1);
            }
        }
        __syncthreads();
    }

    // ---- epilogue: divide by l, bf16 hi/lo split, store a_hi/a_lo ----
    float inv0 = 1.f / l_i[0], inv1 = 1.f / l_i[1];
    int r0 = q0 + wid * 16 + (lane >> 2);
    __nv_bfloat16* Ah = g_bf + BF_AHI + (size_t)(b * SQ) * DM + h * DKH;
    __nv_bfloat16* Al = g_bf + BF_ALO + (size_t)(b * SQ) * DM + h * DKH;
#pragma unroll
    for (int nt = 0; nt < 8; nt++) {
        int col = nt * 8 + (lane & 3) * 2;
        float a0 = o[nt][0] * inv0, a1 = o[nt][1] * inv0;
        float a2 = o[nt][2] * inv1, a3 = o[nt][3] * inv1;
        float h0 = __bfloat162float(__float2bfloat16_rn(a0));
        float h1 = __bfloat162float(__float2bfloat16_rn(a1));
        float h2 = __bfloat162float(__float2bfloat16_rn(a2));
        float h3 = __bfloat162float(__float2bfloat16_rn(a3));
        *(uint32_t*)&Ah[(size_t)r0 * DM + col]       = packbf2(h0, h1);
        *(uint32_t*)&Al[(size_t)r0 * DM + col]       = packbf2(a0 - h0, a1 - h1);
        *(uint32_t*)&Ah[(size_t)(r0 + 8) * DM + col] = packbf2(h2, h3);
        *(uint32_t*)&Al[(size_t)(r0 + 8) * DM + col] = packbf2(a2 - h2, a3 - h3);
    }
}

// ---------------------------------------------------------------------------
extern "C" void kernel_launch(void* const* d_in, const int* in_sizes, int n_in,
                              void* d_out, int out_size)
{
    const float* x  = (const float*)d_in[0];
    const float* Wq = (const float*)d_in[1];
    const float* bq = (const float*)d_in[2];
    const float* Wk = (const float*)d_in[3];
    const float* bk = (const float*)d_in[4];
    const float* Wv = (const float*)d_in[5];
    const float* bv = (const float*)d_in[6];
    const float* Wo = (const float*)d_in[7];
    const float* bo = (const float*)d_in[8];
    float* out = (float*)d_out;

    __nv_bfloat16* bf = nullptr;
    cudaGetSymbolAddress((void**)&bf, g_bf);

    cudaFuncSetAttribute(mm_gemm<0>,
                         cudaFuncAttributeMaxDynamicSharedMemorySize, MM_SMEM);
    cudaFuncSetAttribute(mm_gemm<1>,
                         cudaFuncAttributeMaxDynamicSharedMemorySize, MM_SMEM);
    cudaFuncSetAttribute(mm_gemm<2>,
                         cudaFuncAttributeMaxDynamicSharedMemorySize, MM_SMEM);
    cudaFuncSetAttribute(flash_tc,
                         cudaFuncAttributeMaxDynamicSharedMemorySize, FA3_SMEM);

    // 1) prep: rope table, x split, weight transpose+split
    rope_table_kernel<<<SQ * 32 / 256, 256>>>();
    split_kernel<<<MROWS * DM / 1024, 256>>>(x, bf + BF_XHI, bf + BF_XLO);
    wsplit_kernel<<<dim3(32, 32, 4), dim3(32, 8)>>>(Wq, Wk, Wv, Wo);

    // 2) Q/K/V projections with fused epilogues
    mm_gemm<2><<<dim3(8, 32), 256, MM_SMEM>>>(
        bf + BF_XHI, bf + BF_XLO,
        bf + BF_WT + 0ull * DM * DM, bf + BF_WT + 1ull * DM * DM, bq,
        nullptr, bf + BF_QHI, bf + BF_QLO, 1);
    mm_gemm<2><<<dim3(8, 32), 256, MM_SMEM>>>(
        bf + BF_XHI, bf + BF_XLO,
        bf + BF_WT + 2ull * DM * DM, bf + BF_WT + 3ull * DM * DM, bk,
        nullptr, bf + BF_KHI, bf + BF_KLO, 0);
    mm_gemm<1><<<dim3(8, 32), 256, MM_SMEM>>>(
        bf + BF_XHI, bf + BF_XLO,
        bf + BF_WT + 4ull * DM * DM, bf + BF_WT + 5ull * DM * DM, bv,
        nullptr, bf + BF_VTHI, bf + BF_VTLO, 0);

    // 3) Flash attention (fp16 S + fp16 PV)
    flash_tc<<<dim3(SQ / 128, NB * NH), 256, FA3_SMEM>>>();

    // 4) output projection (fp32 out)
    mm_gemm<0><<<dim3(8, 32), 256, MM_SMEM>>>(
        bf + BF_AHI, bf + BF_ALO,
        bf + BF_WT + 6ull * DM * DM, bf + BF_WT + 7ull * DM * DM, bo,
        out, nullptr, nullptr, 0);
}

// round 17
// speedup vs baseline: 1.5272x; 1.1897x over previous
#include <cuda_runtime.h>
#include <cuda_bf16.h>
#include <cuda_fp16.h>
#include <math.h>
#include <stdint.h>

#define SQ   2048
#define NB   2
#define NH   16
#define DKH  64
#define DM   1024
#define MROWS 4096   // NB*SQ

// ---------------------------------------------------------------------------
// Scratch (__device__ globals; allocation-free rule). All payloads fp16 now.
// ---------------------------------------------------------------------------
__device__ float g_rope[SQ * 32 * 2];                    // cos,sin per (s,j)

// 2-byte element offsets (MROWS*DM = 4M, DM*DM = 1M)
#define BF_XHI  0ull
#define BF_XLO  (1ull * MROWS * DM)
#define BF_WT   (2ull * MROWS * DM)                       // 4 x DM*DM (single fp16)
#define BF_AHI  (BF_WT + 4ull * DM * DM)
#define BF_ALO  (BF_AHI + 1ull * MROWS * DM)
#define BF_QHI  (BF_ALO + 1ull * MROWS * DM)
#define BF_QLO  (BF_QHI + 1ull * MROWS * DM)
#define BF_KHI  (BF_QLO + 1ull * MROWS * DM)
#define BF_VTHI (BF_KHI + 1ull * MROWS * DM)
#define BF_VTLO (BF_VTHI + 1ull * MROWS * DM)
__device__ __half g_bf[BF_VTLO + 1ull * MROWS * DM];

// ---------------------------------------------------------------------------
// Helpers (sm_100-safe: cp.async, ldmatrix, mma.sync only)
// ---------------------------------------------------------------------------
__device__ __forceinline__ uint32_t smem_u32(const void* p) {
    uint32_t a;
    asm("{ .reg .u64 t; cvta.to.shared.u64 t, %1; cvt.u32.u64 %0, t; }"
        : "=r"(a) : "l"(p));
    return a;
}

__device__ __forceinline__ uint32_t sw64(uint32_t off) {
    return off ^ ((off >> 3) & 0x30);
}
__device__ __forceinline__ uint32_t sw128(uint32_t off) {
    return off ^ ((off >> 3) & 0x70);
}

__device__ __forceinline__ void ldm_x4(uint32_t* r, uint32_t addr) {
    asm volatile("ldmatrix.sync.aligned.m8n8.x4.shared.b16 {%0,%1,%2,%3}, [%4];"
                 : "=r"(r[0]), "=r"(r[1]), "=r"(r[2]), "=r"(r[3]) : "r"(addr));
}

__device__ __forceinline__ void mma_f16(float* d, const uint32_t* a,
                                        const uint32_t* b) {
    asm volatile(
        "mma.sync.aligned.m16n8k16.row.col.f32.f16.f16.f32 "
        "{%0,%1,%2,%3}, {%4,%5,%6,%7}, {%8,%9}, {%0,%1,%2,%3};"
        : "+f"(d[0]), "+f"(d[1]), "+f"(d[2]), "+f"(d[3])
        : "r"(a[0]), "r"(a[1]), "r"(a[2]), "r"(a[3]), "r"(b[0]), "r"(b[1]));
}

__device__ __forceinline__ void cp_async16(uint32_t dst, const void* src) {
    asm volatile("cp.async.cg.shared.global [%0], [%1], 16;"
                 :: "r"(dst), "l"(src));
}
#define CP_COMMIT() asm volatile("cp.async.commit_group;" ::: "memory")
#define CP_WAIT(n)  asm volatile("cp.async.wait_group %0;" :: "n"(n) : "memory")

__device__ __forceinline__ uint32_t packh2(float a, float b) {
    __half2 t = __floats2half2_rn(a, b);
    return *(uint32_t*)&t;
}

// ---------------------------------------------------------------------------
// Prep: fp32 -> (fp16 hi, fp16 lo) split, 4 elems/thread
// ---------------------------------------------------------------------------
__global__ __launch_bounds__(256) void split_kernel(
    const float* __restrict__ src, __half* __restrict__ hi,
    __half* __restrict__ lo)
{
    size_t i = (size_t)(blockIdx.x * 256 + threadIdx.x) * 4;
    float4 v = *(const float4*)(src + i);
    float h0 = __half2float(__float2half_rn(v.x));
    float h1 = __half2float(__float2half_rn(v.y));
    float h2 = __half2float(__float2half_rn(v.z));
    float h3 = __half2float(__float2half_rn(v.w));
    uint2 hv, lv;
    hv.x = packh2(h0, h1); hv.y = packh2(h2, h3);
    lv.x = packh2(v.x - h0, v.y - h1);
    lv.y = packh2(v.z - h2, v.w - h3);
    *(uint2*)&hi[i] = hv;
    *(uint2*)&lo[i] = lv;
}

// ---------------------------------------------------------------------------
// Prep: transpose the 4 weight matrices W[k][n] -> Wt[n][k] single fp16
// ---------------------------------------------------------------------------
__global__ __launch_bounds__(256) void wsplit_kernel(
    const float* __restrict__ W0, const float* __restrict__ W1,
    const float* __restrict__ W2, const float* __restrict__ W3)
{
    __shared__ float t[32][33];
    const float* W = (blockIdx.z == 0) ? W0 : (blockIdx.z == 1) ? W1
                   : (blockIdx.z == 2) ? W2 : W3;
    __half* wt = g_bf + BF_WT + (size_t)blockIdx.z * DM * DM;
    int tx = threadIdx.x, ty = threadIdx.y;
    int n = blockIdx.x * 32 + tx;
#pragma unroll
    for (int i = 0; i < 32; i += 8)
        t[ty + i][tx] = W[(size_t)(blockIdx.y * 32 + ty + i) * DM + n];
    __syncthreads();
#pragma unroll
    for (int i = 0; i < 32; i += 8) {
        size_t o = (size_t)(blockIdx.x * 32 + ty + i) * DM + blockIdx.y * 32 + tx;
        wt[o] = __float2half_rn(t[tx][ty + i]);
    }
}

// ---------------------------------------------------------------------------
// RoPE cos/sin table: (s, j) -> g_rope[2*(s*32+j)] = {cos, sin}
// ---------------------------------------------------------------------------
__global__ __launch_bounds__(256) void rope_table_kernel()
{
    int i = blockIdx.x * 256 + threadIdx.x;   // 0 .. 65535
    int s = i >> 5, j = i & 31;
    float invf = (float)pow(10000.0, -(double)j / 32.0);
    float ang = (float)s * invf;
    float sn, c;
    sincosf(ang, &sn, &c);
    g_rope[2 * i]     = c;
    g_rope[2 * i + 1] = sn;
}

// ---------------------------------------------------------------------------
// fp16-split GEMM: A fp16 hi/lo x W single fp16, 2 MMAs. 3-stage cp.async
// pipeline (3 tiles/stage = 24 KB). Fused epilogues as before.
// MODE 0: C = acc + bias (fp32, row-major)
// MODE 1: Vt hi/lo fp16, transposed write [(bh*64+d)][s]  (vectorized x4)
// MODE 2: RoPE + split. scaleQ=1: Q fp16 hi/lo (0.125 scale);
//                       scaleQ=0: K single fp16.
// ---------------------------------------------------------------------------
#define KCH 32
#define NKT (DM / KCH)             // 32 chunks
#define STG_T 8192
#define STG_B (3 * STG_T)          // 24 KB per stage
#define MM_SMEM (3 * STG_B + 1024)

template <int MODE>
__global__ __launch_bounds__(256, 2) void mm_gemm(
    const __half* __restrict__ Ahi, const __half* __restrict__ Alo,
    const __half* __restrict__ Bw,
    const float* __restrict__ bias, float* __restrict__ C,
    __half* __restrict__ Dhi, __half* __restrict__ Dlo,
    int scaleQ)
{
    extern __shared__ char smraw[];
    const uint32_t sbase = (smem_u32(smraw) + 1023) & ~1023u;

    const int tid  = threadIdx.x;
    const int wid  = tid >> 5, lane = tid & 31;
    const int m0   = blockIdx.y * 128, n0 = blockIdx.x * 128;
    const int wm   = (wid >> 2) * 64, wn = (wid & 3) * 32;

    float acc[4][4][4];
#pragma unroll
    for (int i = 0; i < 4; i++)
#pragma unroll
        for (int j = 0; j < 4; j++)
#pragma unroll
            for (int r = 0; r < 4; r++) acc[i][j][r] = 0.f;

    auto load_stage = [&](int kt, int slot) {
        const uint32_t bb = sbase + slot * STG_B;
#pragma unroll
        for (int it = 0; it < 6; it++) {
            int i = it * 256 + tid;        // 0..1535
            int tile = i >> 9, idx = i & 511;
            int r = idx >> 2, c = idx & 3;
            uint32_t dst = bb + tile * STG_T + sw64((uint32_t)(r * 64 + c * 16));
            size_t off = (tile < 2)
                ? (size_t)(m0 + r) * DM + kt * KCH + c * 8
                : (size_t)(n0 + r) * DM + kt * KCH + c * 8;
            const __half* src =
                (tile == 0) ? Ahi + off : (tile == 1) ? Alo + off : Bw + off;
            cp_async16(dst, src);
        }
    };

    load_stage(0, 0); CP_COMMIT();
    load_stage(1, 1); CP_COMMIT();

    int slot = 0;
    for (int kt = 0; kt < NKT; kt++) {
        CP_WAIT(1);
        __syncthreads();
        if (kt + 2 < NKT) {
            int ns = slot + 2; if (ns >= 3) ns -= 3;
            load_stage(kt + 2, ns);
            CP_COMMIT();
        } else {
            CP_COMMIT();
        }

        const uint32_t bb = sbase + slot * STG_B;
#pragma unroll
        for (int ks = 0; ks < 2; ks++) {
            uint32_t ah[4][4], al[4][4];
#pragma unroll
            for (int mt = 0; mt < 4; mt++) {
                int row = wm + mt * 16 + (lane & 15);
                int c = ks * 2 + (lane >> 4);
                uint32_t so = sw64((uint32_t)(row * 64 + c * 16));
                ldm_x4(ah[mt], bb + 0 * STG_T + so);
                ldm_x4(al[mt], bb + 1 * STG_T + so);
            }
            uint32_t bw[4][2];
#pragma unroll
            for (int np = 0; np < 2; np++) {
                int row = wn + np * 16 + (lane & 7) + ((lane >> 4) << 3);
                int c = ks * 2 + ((lane >> 3) & 1);
                uint32_t so = sw64((uint32_t)(row * 64 + c * 16));
                uint32_t r4[4];
                ldm_x4(r4, bb + 2 * STG_T + so);
                bw[np * 2][0] = r4[0]; bw[np * 2][1] = r4[1];
                bw[np * 2 + 1][0] = r4[2]; bw[np * 2 + 1][1] = r4[3];
            }
#pragma unroll
            for (int mt = 0; mt < 4; mt++)
#pragma unroll
                for (int nt = 0; nt < 4; nt++) {
                    mma_f16(acc[mt][nt], ah[mt], bw[nt]);
                    mma_f16(acc[mt][nt], al[mt], bw[nt]);
                }
        }
        if (++slot == 3) slot = 0;
    }

    const int g = lane >> 2, t = lane & 3;

    if (MODE == 0) {
#pragma unroll
        for (int mt = 0; mt < 4; mt++) {
            int r0 = m0 + wm + mt * 16 + g;
#pragma unroll
            for (int nt = 0; nt < 4; nt++) {
                int col = n0 + wn + nt * 8 + t * 2;
                float2 bv = *(const float2*)&bias[col];
                float2 o0, o1;
                o0.x = acc[mt][nt][0] + bv.x;
                o0.y = acc[mt][nt][1] + bv.y;
                o1.x = acc[mt][nt][2] + bv.x;
                o1.y = acc[mt][nt][3] + bv.y;
                *(float2*)&C[(size_t)r0 * DM + col] = o0;
                *(float2*)&C[(size_t)(r0 + 8) * DM + col] = o1;
            }
        }
        return;
    }

    // ---- staged epilogues: tile -> smem fp32 [128][129] (reuse stages) ----
    __syncthreads();
    float* csm = (float*)smraw;
#pragma unroll
    for (int mt = 0; mt < 4; mt++) {
        int r0 = wm + mt * 16 + g;
#pragma unroll
        for (int nt = 0; nt < 4; nt++) {
            int col = wn + nt * 8 + t * 2;
            float2 bv = *(const float2*)&bias[n0 + col];
            csm[r0 * 129 + col]           = acc[mt][nt][0] + bv.x;
            csm[r0 * 129 + col + 1]       = acc[mt][nt][1] + bv.y;
            csm[(r0 + 8) * 129 + col]     = acc[mt][nt][2] + bv.x;
            csm[(r0 + 8) * 129 + col + 1] = acc[mt][nt][3] + bv.y;
        }
    }
    __syncthreads();

    if (MODE == 1) {
        // ---- Vt: [(bh*64+d)][s] fp16 hi/lo ----
#pragma unroll
        for (int i = 0; i < 16; i++) {
            int idx = i * 256 + tid;
            int drow = idx >> 5, s4 = (idx & 31) * 4;
            float v0 = csm[(s4 + 0) * 129 + drow];
            float v1 = csm[(s4 + 1) * 129 + drow];
            float v2 = csm[(s4 + 2) * 129 + drow];
            float v3 = csm[(s4 + 3) * 129 + drow];
            int m = m0 + s4, b = m >> 11, s = m & (SQ - 1);
            int ncol = n0 + drow, h = ncol >> 6, d = ncol & 63;
            size_t o = (size_t)((b * NH + h) * DKH + d) * SQ + s;
            float h0 = __half2float(__float2half_rn(v0));
            float h1 = __half2float(__float2half_rn(v1));
            float h2 = __half2float(__float2half_rn(v2));
            float h3 = __half2float(__float2half_rn(v3));
            uint2 hv, lv;
            hv.x = packh2(h0, h1); hv.y = packh2(h2, h3);
            lv.x = packh2(v0 - h0, v1 - h1);
            lv.y = packh2(v2 - h2, v3 - h3);
            *(uint2*)&Dhi[o] = hv;
            *(uint2*)&Dlo[o] = lv;
        }
    } else {
        // ---- MODE 2: RoPE + split to fp16 ----
        float sc = scaleQ ? 0.125f : 1.0f;
#pragma unroll
        for (int i = 0; i < 16; i++) {
            int idx = i * 256 + tid;
            int row = idx >> 5, n4 = (idx & 31) * 4;
            int d = n4 & 63, j = d & 31, hb = n4 & 64;
            int m = m0 + row, s = m & (SQ - 1);
            const float* cr = csm + row * 129 + hb;
            float r[4];
            bool first = (d < 32);
#pragma unroll
            for (int e = 0; e < 4; e++) {
                int jj = j + e;
                float x1 = cr[jj], x2 = cr[jj + 32];
                float2 cs = *(const float2*)&g_rope[2 * (s * 32 + jj)];
                r[e] = first ? (x1 * cs.x - x2 * cs.y)
                             : (x1 * cs.y + x2 * cs.x);
                r[e] *= sc;
            }
            size_t o = (size_t)m * DM + n0 + n4;
            if (scaleQ) {
                float h0 = __half2float(__float2half_rn(r[0]));
                float h1 = __half2float(__float2half_rn(r[1]));
                float h2 = __half2float(__float2half_rn(r[2]));
                float h3 = __half2float(__float2half_rn(r[3]));
                uint2 hv, lv;
                hv.x = packh2(h0, h1); hv.y = packh2(h2, h3);
                lv.x = packh2(r[0] - h0, r[1] - h1);
                lv.y = packh2(r[2] - h2, r[3] - h3);
                *(uint2*)&Dhi[o] = hv;
                *(uint2*)&Dlo[o] = lv;
            } else {
                uint2 hv;
                hv.x = packh2(r[0], r[1]); hv.y = packh2(r[2], r[3]);
                *(uint2*)&Dhi[o] = hv;
            }
        }
    }
}

// ---------------------------------------------------------------------------
// Tensor-core flash attention (all fp16 MMAs, unchanged from R16 except
// epilogue packs a_hi/a_lo as fp16).
// ---------------------------------------------------------------------------
#define FS_QH 0
#define FS_QL 16384
#define FS_ST 32768
#define FS_STB 24576
#define FA3_SMEM (FS_ST + 2 * FS_STB + 1024)

__global__ __launch_bounds__(256, 2) void flash_tc()
{
    extern __shared__ char smraw[];
    const uint32_t sb = (smem_u32(smraw) + 1023) & ~1023u;

    const int tid = threadIdx.x;
    const int wid = tid >> 5, lane = tid & 31;
    const int bh = blockIdx.y, b = bh >> 4, h = bh & 15;
    const int q0 = blockIdx.x * 128;

    const __half* Qh = g_bf + BF_QHI + (size_t)(b * SQ + q0) * DM + h * DKH;
    const __half* Ql = g_bf + BF_QLO + (size_t)(b * SQ + q0) * DM + h * DKH;
    const __half* Kh = g_bf + BF_KHI + (size_t)(b * SQ) * DM + h * DKH;
    const __half* Vh = g_bf + BF_VTHI + (size_t)(bh * DKH) * SQ;
    const __half* Vl = g_bf + BF_VTLO + (size_t)(bh * DKH) * SQ;

#pragma unroll
    for (int it = 0; it < 8; it++) {
        int i = it * 256 + tid;            // 0..2047
        int arr = i >> 10, idx = i & 1023;
        int row = idx >> 3, c8 = idx & 7;
        const __half* src = (arr ? Ql : Qh) + (size_t)row * DM + c8 * 8;
        uint32_t dst = sb + (arr ? FS_QL : FS_QH)
                     + sw128((uint32_t)(row * 128 + c8 * 16));
        cp_async16(dst, src);
    }
    CP_COMMIT();

    auto load_stage = [&](int ktile, int buf) {
        const uint32_t bb = sb + FS_ST + buf * FS_STB;
#pragma unroll
        for (int it = 0; it < 6; it++) {
            int i = it * 256 + tid;        // 0..1535
            int tile = i >> 9, idx = i & 511;
            int row = idx >> 3, c8 = idx & 7;
            const __half* src;
            if (tile == 0) {
                src = Kh + (size_t)(ktile * 64 + row) * DM + c8 * 8;
            } else {
                src = ((tile == 2) ? Vl : Vh)
                    + (size_t)row * SQ + ktile * 64 + c8 * 8;
            }
            uint32_t dst = bb + (tile << 13)
                         + sw128((uint32_t)(row * 128 + c8 * 16));
            cp_async16(dst, src);
        }
    };

    load_stage(0, 0);
    CP_COMMIT();
    CP_WAIT(1);                // Q arrived
    __syncthreads();

    uint32_t qh[4][4], ql[4][4];
#pragma unroll
    for (int kt = 0; kt < 4; kt++) {
        int row = wid * 16 + (lane & 15);
        uint32_t so = sw128((uint32_t)(row * 128 + kt * 32 + (lane >> 4) * 16));
        ldm_x4(qh[kt], sb + FS_QH + so);
        ldm_x4(ql[kt], sb + FS_QL + so);
    }

    float m_i[2] = {-1e30f, -1e30f};
    float l_i[2] = {0.f, 0.f};
    float o[8][4];
#pragma unroll
    for (int nt = 0; nt < 8; nt++)
#pragma unroll
        for (int r = 0; r < 4; r++) o[nt][r] = 0.f;

    for (int ktile = 0; ktile < SQ / 64; ktile++) {
        const int buf = ktile & 1;
        if (ktile < SQ / 64 - 1) {
            load_stage(ktile + 1, buf ^ 1);
            CP_COMMIT();
            CP_WAIT(1);
        } else {
            CP_WAIT(0);
        }
        __syncthreads();

        const uint32_t bb = sb + FS_ST + buf * FS_STB;
        const uint32_t KH = bb, VH = bb + 8192, VL = bb + 16384;

        // ---- S = Q K^T : Q fp16 hi/lo x K single fp16, 2 MMAs ----
        float sacc[8][4];
#pragma unroll
        for (int nt = 0; nt < 8; nt++)
#pragma unroll
            for (int r = 0; r < 4; r++) sacc[nt][r] = 0.f;

#pragma unroll
        for (int kt = 0; kt < 4; kt++) {
            uint32_t khf[8][2];
#pragma unroll
            for (int np = 0; np < 4; np++) {
                int row = np * 16 + (lane & 7) + ((lane >> 4) << 3);
                uint32_t so = sw128((uint32_t)(row * 128 + kt * 32
                                               + ((lane >> 3) & 1) * 16));
                uint32_t r4[4];
                ldm_x4(r4, KH + so);
                khf[np * 2][0] = r4[0]; khf[np * 2][1] = r4[1];
                khf[np * 2 + 1][0] = r4[2]; khf[np * 2 + 1][1] = r4[3];
            }
#pragma unroll
            for (int nt = 0; nt < 8; nt++) {
                mma_f16(sacc[nt], qh[kt], khf[nt]);
                mma_f16(sacc[nt], ql[kt], khf[nt]);
            }
        }

        float mx0 = -1e30f, mx1 = -1e30f;
#pragma unroll
        for (int nt = 0; nt < 8; nt++) {
            mx0 = fmaxf(mx0, fmaxf(sacc[nt][0], sacc[nt][1]));
            mx1 = fmaxf(mx1, fmaxf(sacc[nt][2], sacc[nt][3]));
        }
        mx0 = fmaxf(mx0, __shfl_xor_sync(0xffffffffu, mx0, 1));
        mx0 = fmaxf(mx0, __shfl_xor_sync(0xffffffffu, mx0, 2));
        mx1 = fmaxf(mx1, __shfl_xor_sync(0xffffffffu, mx1, 1));
        mx1 = fmaxf(mx1, __shfl_xor_sync(0xffffffffu, mx1, 2));
        float mn0 = fmaxf(m_i[0], mx0), mn1 = fmaxf(m_i[1], mx1);
        float al0 = __expf(m_i[0] - mn0), al1 = __expf(m_i[1] - mn1);
        float rs0 = 0.f, rs1 = 0.f;
#pragma unroll
        for (int nt = 0; nt < 8; nt++) {
            sacc[nt][0] = __expf(sacc[nt][0] - mn0);
            sacc[nt][1] = __expf(sacc[nt][1] - mn0);
            sacc[nt][2] = __expf(sacc[nt][2] - mn1);
            sacc[nt][3] = __expf(sacc[nt][3] - mn1);
            rs0 += sacc[nt][0] + sacc[nt][1];
            rs1 += sacc[nt][2] + sacc[nt][3];
        }
        rs0 += __shfl_xor_sync(0xffffffffu, rs0, 1);
        rs0 += __shfl_xor_sync(0xffffffffu, rs0, 2);
        rs1 += __shfl_xor_sync(0xffffffffu, rs1, 1);
        rs1 += __shfl_xor_sync(0xffffffffu, rs1, 2);
        l_i[0] = l_i[0] * al0 + rs0;
        l_i[1] = l_i[1] * al1 + rs1;
        m_i[0] = mn0; m_i[1] = mn1;
#pragma unroll
        for (int nt = 0; nt < 8; nt++) {
            o[nt][0] *= al0; o[nt][1] *= al0;
            o[nt][2] *= al1; o[nt][3] *= al1;
        }

        // ---- PV: P single fp16, V fp16 hi/lo (2 MMAs per pair) ----
#pragma unroll
        for (int t = 0; t < 4; t++) {
            uint32_t ahf[4];
            ahf[0] = packh2(sacc[2 * t][0], sacc[2 * t][1]);
            ahf[1] = packh2(sacc[2 * t][2], sacc[2 * t][3]);
            ahf[2] = packh2(sacc[2 * t + 1][0], sacc[2 * t + 1][1]);
            ahf[3] = packh2(sacc[2 * t + 1][2], sacc[2 * t + 1][3]);
#pragma unroll
            for (int np = 0; np < 4; np++) {
                uint32_t r4[4], vh0[2], vh1[2], vl0[2], vl1[2];
                int row = np * 16 + (lane & 7) + ((lane >> 4) << 3);
                uint32_t so = sw128((uint32_t)(row * 128 + t * 32
                                               + ((lane >> 3) & 1) * 16));
                ldm_x4(r4, VH + so);
                vh0[0] = r4[0]; vh0[1] = r4[1]; vh1[0] = r4[2]; vh1[1] = r4[3];
                ldm_x4(r4, VL + so);
                vl0[0] = r4[0]; vl0[1] = r4[1]; vl1[0] = r4[2]; vl1[1] = r4[3];
                mma_f16(o[np * 2], ahf, vh0);
                mma_f16(o[np * 2], ahf, vl0);
                mma_f16(o[np * 2 + 1], ahf, vh1);
                mma_f16(o[np * 2 + 1], ahf, vl1);
            }
        }
        __syncthreads();
    }

    // ---- epilogue: divide by l, fp16 hi/lo split, store a_hi/a_lo ----
    float inv0 = 1.f / l_i[0], inv1 = 1.f / l_i[1];
    int r0 = q0 + wid * 16 + (lane >> 2);
    __half* Ah = g_bf + BF_AHI + (size_t)(b * SQ) * DM + h * DKH;
    __half* Al = g_bf + BF_ALO + (size_t)(b * SQ) * DM + h * DKH;
#pragma unroll
    for (int nt = 0; nt < 8; nt++) {
        int col = nt * 8 + (lane & 3) * 2;
        float a0 = o[nt][0] * inv0, a1 = o[nt][1] * inv0;
        float a2 = o[nt][2] * inv1, a3 = o[nt][3] * inv1;
        float h0 = __half2float(__float2half_rn(a0));
        float h1 = __half2float(__float2half_rn(a1));
        float h2 = __half2float(__float2half_rn(a2));
        float h3 = __half2float(__float2half_rn(a3));
        *(uint32_t*)&Ah[(size_t)r0 * DM + col]       = packh2(h0, h1);
        *(uint32_t*)&Al[(size_t)r0 * DM + col]       = packh2(a0 - h0, a1 - h1);
        *(uint32_t*)&Ah[(size_t)(r0 + 8) * DM + col] = packh2(h2, h3);
        *(uint32_t*)&Al[(size_t)(r0 + 8) * DM + col] = packh2(a2 - h2, a3 - h3);
    }
}

// ---------------------------------------------------------------------------
extern "C" void kernel_launch(void* const* d_in, const int* in_sizes, int n_in,
                              void* d_out, int out_size)
{
    const float* x  = (const float*)d_in[0];
    const float* Wq = (const float*)d_in[1];
    const float* bq = (const float*)d_in[2];
    const float* Wk = (const float*)d_in[3];
    const float* bk = (const float*)d_in[4];
    const float* Wv = (const float*)d_in[5];
    const float* bv = (const float*)d_in[6];
    const float* Wo = (const float*)d_in[7];
    const float* bo = (const float*)d_in[8];
    float* out = (float*)d_out;

    __half* bf = nullptr;
    cudaGetSymbolAddress((void**)&bf, g_bf);

    cudaFuncSetAttribute(mm_gemm<0>,
                         cudaFuncAttributeMaxDynamicSharedMemorySize, MM_SMEM);
    cudaFuncSetAttribute(mm_gemm<1>,
                         cudaFuncAttributeMaxDynamicSharedMemorySize, MM_SMEM);
    cudaFuncSetAttribute(mm_gemm<2>,
                         cudaFuncAttributeMaxDynamicSharedMemorySize, MM_SMEM);
    cudaFuncSetAttribute(flash_tc,
                         cudaFuncAttributeMaxDynamicSharedMemorySize, FA3_SMEM);

    // 1) prep: rope table, x split (fp16), weight transpose (fp16)
    rope_table_kernel<<<SQ * 32 / 256, 256>>>();
    split_kernel<<<MROWS * DM / 1024, 256>>>(x, bf + BF_XHI, bf + BF_XLO);
    wsplit_kernel<<<dim3(32, 32, 4), dim3(32, 8)>>>(Wq, Wk, Wv, Wo);

    // 2) Q/K/V projections with fused epilogues (2-MMA fp16)
    mm_gemm<2><<<dim3(8, 32), 256, MM_SMEM>>>(
        bf + BF_XHI, bf + BF_XLO, bf + BF_WT + 0ull * DM * DM, bq,
        nullptr, bf + BF_QHI, bf + BF_QLO, 1);
    mm_gemm<2><<<dim3(8, 32), 256, MM_SMEM>>>(
        bf + BF_XHI, bf + BF_XLO, bf + BF_WT + 1ull * DM * DM, bk,
        nullptr, bf + BF_KHI, nullptr, 0);
    mm_gemm<1><<<dim3(8, 32), 256, MM_SMEM>>>(
        bf + BF_XHI, bf + BF_XLO, bf + BF_WT + 2ull * DM * DM, bv,
        nullptr, bf + BF_VTHI, bf + BF_VTLO, 0);

    // 3) Flash attention (all-fp16 MMAs)
    flash_tc<<<dim3(SQ / 128, NB * NH), 256, FA3_SMEM>>>();

    // 4) output projection (fp32 out)
    mm_gemm<0><<<dim3(8, 32), 256, MM_SMEM>>>(
        bf + BF_AHI, bf + BF_ALO, bf + BF_WT + 3ull * DM * DM, bo,
        out, nullptr, nullptr, 0);
}